// round 10
// baseline (speedup 1.0000x reference)
#include <cuda_runtime.h>
#include <cuda_fp16.h>
#include <math.h>
#include <stdint.h>

// ---------------- Problem constants ----------------
#define Bb 8
#define Tt 8192
#define Cc 512
#define Hh 8
#define Dd 64
#define NN (Bb*Tt)         // 65536 tokens
#define BH (Bb*Hh)         // 64
#define KV_SPLIT 16

// ---------------- Scratch (device globals) ----------------
__device__ __half g_Xh[(size_t)NN*Cc];
__device__ __half g_Wh[(size_t)4*Cc*Cc];
__device__ __half g_Qh[(size_t)NN*Cc];
__device__ __half g_Kh[(size_t)NN*Cc];
__device__ __half g_Vh[(size_t)NN*Cc];
__device__ __half g_Yh[(size_t)NN*Cc];
__device__ float  g_KV[(size_t)BH*Dd*Dd];
__device__ float  g_Ksum[(size_t)BH*Dd];

// ---------------- helpers ----------------
__device__ __forceinline__ uint32_t smem_u32(const void* p) {
    uint32_t a;
    asm("{ .reg .u64 t; cvta.to.shared.u64 t, %1; cvt.u32.u64 %0, t; }" : "=r"(a) : "l"(p));
    return a;
}
#define CP_ASYNC16(dst, src) \
    asm volatile("cp.async.cg.shared.global [%0], [%1], 16;" :: "r"(dst), "l"(src) : "memory")
#define CP_COMMIT() asm volatile("cp.async.commit_group;" ::: "memory")
#define CP_WAIT(n)  asm volatile("cp.async.wait_group %0;" :: "n"(n) : "memory")

__device__ __forceinline__ void ldsm_x4(uint32_t* r, uint32_t addr) {
    asm volatile("ldmatrix.sync.aligned.m8n8.x4.shared.b16 {%0,%1,%2,%3}, [%4];"
                 : "=r"(r[0]), "=r"(r[1]), "=r"(r[2]), "=r"(r[3]) : "r"(addr));
}
__device__ __forceinline__ void mma_f16(float* c, const uint32_t* a, uint32_t b0, uint32_t b1) {
    asm volatile("mma.sync.aligned.m16n8k16.row.col.f32.f16.f16.f32 "
                 "{%0,%1,%2,%3},{%4,%5,%6,%7},{%8,%9},{%0,%1,%2,%3};"
                 : "+f"(c[0]), "+f"(c[1]), "+f"(c[2]), "+f"(c[3])
                 : "r"(a[0]), "r"(a[1]), "r"(a[2]), "r"(a[3]), "r"(b0), "r"(b1));
}

// ---------------- GEMM config (fp16, 128x128 CTA, 8 warps of 64x32) ----------------
#define BM 128
#define BN 128
#define BKH 64
#define NKH (Cc / BKH)
#define ASTRH 72
#define TILEH (BM * ASTRH)
#define STAGEH (2 * TILEH)
#define NSTG 3
#define GEMM_SMEM (NSTG * STAGEH * 2)   // 110592 bytes

__device__ __forceinline__ void gemm_core(
    const __half* __restrict__ A, const __half* __restrict__ B,
    int m0, int n0, __half* smh, float acc[4][4][4])
{
    const int tid = threadIdx.x;
    const int wid = tid >> 5;
    const int lane = tid & 31;
    const int m_warp = (wid >> 2) * 64;
    const int n_warp = (wid & 3) * 32;

    const int g8 = lane >> 3;
    const int r8 = lane & 7;
    const int a_row_l = r8 + (g8 & 1) * 8;
    const int a_kb    = (g8 >> 1) * 16;
    const int b_row_l = r8 + (g8 >> 1) * 8;
    const int b_kb    = (g8 & 1) * 16;

    const uint32_t smb = smem_u32(smh);

#pragma unroll
    for (int i = 0; i < 4; i++)
#pragma unroll
        for (int j = 0; j < 4; j++)
#pragma unroll
            for (int k = 0; k < 4; k++) acc[i][j][k] = 0.f;

    auto load_stage = [&](int kc, int s) {
        const __half* gA = A + (size_t)m0 * Cc + kc * BKH;
        const __half* gB = B + (size_t)n0 * Cc + kc * BKH;
        uint32_t dA = smb + (uint32_t)(s * STAGEH) * 2;
        uint32_t dB = dA + (uint32_t)TILEH * 2;
#pragma unroll
        for (int i = 0; i < 4; i++) {
            int idx = tid + i * 256;
            int row = idx >> 3;
            int c8 = idx & 7;
            CP_ASYNC16(dA + (uint32_t)(row * ASTRH + c8 * 8) * 2, gA + (size_t)row * Cc + c8 * 8);
        }
#pragma unroll
        for (int i = 0; i < 4; i++) {
            int idx = tid + i * 256;
            int row = idx >> 3;
            int c8 = idx & 7;
            CP_ASYNC16(dB + (uint32_t)(row * ASTRH + c8 * 8) * 2, gB + (size_t)row * Cc + c8 * 8);
        }
        CP_COMMIT();
    };

    load_stage(0, 0);
    load_stage(1, 1);

    for (int kt = 0; kt < NKH; kt++) {
        if (kt < NKH - 1) CP_WAIT(1); else CP_WAIT(0);
        __syncthreads();
        if (kt + 2 < NKH) load_stage(kt + 2, (kt + 2) % 3);

        const int s = kt % 3;
        const uint32_t aB = smb + (uint32_t)(s * STAGEH) * 2
                          + (uint32_t)((m_warp + a_row_l) * ASTRH) * 2 + a_kb;
        const uint32_t bB = smb + (uint32_t)(s * STAGEH + TILEH) * 2
                          + (uint32_t)((n_warp + b_row_l) * ASTRH) * 2 + b_kb;

#pragma unroll
        for (int ks = 0; ks < 4; ks++) {
            uint32_t af[4][4];
#pragma unroll
            for (int mi = 0; mi < 4; mi++)
                ldsm_x4(af[mi], aB + (uint32_t)(mi * 16 * ASTRH) * 2 + ks * 32);
            uint32_t bf[2][4];
#pragma unroll
            for (int p = 0; p < 2; p++)
                ldsm_x4(bf[p], bB + (uint32_t)(p * 16 * ASTRH) * 2 + ks * 32);
#pragma unroll
            for (int mi = 0; mi < 4; mi++) {
#pragma unroll
                for (int p = 0; p < 2; p++) {
                    mma_f16(acc[mi][p * 2 + 0], af[mi], bf[p][0], bf[p][1]);
                    mma_f16(acc[mi][p * 2 + 1], af[mi], bf[p][2], bf[p][3]);
                }
            }
        }
    }
}

__device__ __forceinline__ void epilogue_h(
    float acc[4][4][4], const float* bias, __half* outp, int m0, int n0, int act)
{
    const int tid = threadIdx.x;
    const int wid = tid >> 5;
    const int lane = tid & 31;
    const int m_warp = (wid >> 2) * 64;
    const int n_warp = (wid & 3) * 32;
    const int r_lo = lane >> 2;
    const int c_off = (lane & 3) * 2;
#pragma unroll
    for (int mi = 0; mi < 4; mi++) {
#pragma unroll
        for (int nj = 0; nj < 4; nj++) {
            int col = n0 + n_warp + nj * 8 + c_off;
            float b0 = bias[col], b1 = bias[col + 1];
#pragma unroll
            for (int half_ = 0; half_ < 2; half_++) {
                int row = m0 + m_warp + mi * 16 + r_lo + half_ * 8;
                float v0 = acc[mi][nj][half_ * 2 + 0] + b0;
                float v1 = acc[mi][nj][half_ * 2 + 1] + b1;
                if (act) {
                    v0 = (v0 > 0.f) ? v0 + 1.f : expf(v0);
                    v1 = (v1 > 0.f) ? v1 + 1.f : expf(v1);
                }
                __half2 hv = __floats2half2_rn(v0, v1);
                *(__half2*)(outp + (size_t)row * Cc + col) = hv;
            }
        }
    }
}

// K,V projections: grid (NN/BM, 8). seg = by>>2: 0=K (ELU+1), 1=V.
__global__ __launch_bounds__(256, 2)
void gemm_kv(const __half* __restrict__ X, const __half* __restrict__ W,
             const float* __restrict__ bk, const float* __restrict__ bv,
             __half* __restrict__ K, __half* __restrict__ V)
{
    extern __shared__ __half smh[];
    const int seg = blockIdx.y >> 2;
    const int n0 = (blockIdx.y & 3) * BN;
    const int m0 = blockIdx.x * BM;
    const __half* B = W + (size_t)(1 + seg) * Cc * Cc;   // Wk, Wv

    float acc[4][4][4];
    gemm_core(X, B, m0, n0, smh, acc);
    epilogue_h(acc, seg ? bv : bk, seg ? V : K, m0, n0, seg == 0);
}

// Q projection: grid (NN/BM, 4). ELU+1.
__global__ __launch_bounds__(256, 2)
void gemm_q(const __half* __restrict__ X, const __half* __restrict__ W,
            const float* __restrict__ bq, __half* __restrict__ Q)
{
    extern __shared__ __half smh[];
    const int m0 = blockIdx.x * BM;
    const int n0 = blockIdx.y * BN;

    float acc[4][4][4];
    gemm_core(X, W, m0, n0, smh, acc);   // Wq at offset 0
    epilogue_h(acc, bq, Q, m0, n0, 1);
}

// Output projection: f32 store, no activation.
__global__ __launch_bounds__(256, 2)
void gemm_out(const __half* __restrict__ Y, const __half* __restrict__ W,
              const float* __restrict__ bias, float* __restrict__ outp)
{
    extern __shared__ __half smh[];
    const int m0 = blockIdx.x * BM;
    const int n0 = blockIdx.y * BN;

    float acc[4][4][4];
    gemm_core(Y, W, m0, n0, smh, acc);

    const int tid = threadIdx.x;
    const int wid = tid >> 5;
    const int lane = tid & 31;
    const int m_warp = (wid >> 2) * 64;
    const int n_warp = (wid & 3) * 32;
    const int r_lo = lane >> 2;
    const int c_off = (lane & 3) * 2;
#pragma unroll
    for (int mi = 0; mi < 4; mi++) {
#pragma unroll
        for (int nj = 0; nj < 4; nj++) {
            int col = n0 + n_warp + nj * 8 + c_off;
            float b0 = bias[col], b1 = bias[col + 1];
#pragma unroll
            for (int half_ = 0; half_ < 2; half_++) {
                int row = m0 + m_warp + mi * 16 + r_lo + half_ * 8;
                float v0 = acc[mi][nj][half_ * 2 + 0] + b0;
                float v1 = acc[mi][nj][half_ * 2 + 1] + b1;
                *(float2*)(outp + (size_t)row * Cc + col) = make_float2(v0, v1);
            }
        }
    }
}

// ---------------- f32 -> f16 conversions ----------------
__global__ __launch_bounds__(256) void cvt_f16(const float4* __restrict__ src,
                                               uint4* __restrict__ dst, int n8)
{
    int i = blockIdx.x * blockDim.x + threadIdx.x;
    if (i < n8) {
        float4 a = src[2 * i], b = src[2 * i + 1];
        __half2 h0 = __floats2half2_rn(a.x, a.y);
        __half2 h1 = __floats2half2_rn(a.z, a.w);
        __half2 h2 = __floats2half2_rn(b.x, b.y);
        __half2 h3 = __floats2half2_rn(b.z, b.w);
        uint4 o;
        o.x = *(uint32_t*)&h0; o.y = *(uint32_t*)&h1;
        o.z = *(uint32_t*)&h2; o.w = *(uint32_t*)&h3;
        dst[i] = o;
    }
}

__global__ __launch_bounds__(256) void cvt_w(
    const float4* __restrict__ w0, const float4* __restrict__ w1,
    const float4* __restrict__ w2, const float4* __restrict__ w3,
    uint4* __restrict__ dst)
{
    const int w8 = Cc * Cc / 8;
    int i = blockIdx.x * blockDim.x + threadIdx.x;
    if (i >= 4 * w8) return;
    int seg = i / w8, j = i - seg * w8;
    const float4* src = (seg == 0) ? w0 : (seg == 1) ? w1 : (seg == 2) ? w2 : w3;
    float4 a = src[2 * j], b = src[2 * j + 1];
    __half2 h0 = __floats2half2_rn(a.x, a.y);
    __half2 h1 = __floats2half2_rn(a.z, a.w);
    __half2 h2 = __floats2half2_rn(b.x, b.y);
    __half2 h3 = __floats2half2_rn(b.z, b.w);
    uint4 o;
    o.x = *(uint32_t*)&h0; o.y = *(uint32_t*)&h1;
    o.z = *(uint32_t*)&h2; o.w = *(uint32_t*)&h3;
    dst[i] = o;
}

// ---------------- attention-side kernels ----------------
__global__ void zero_kv()
{
    int i = blockIdx.x * blockDim.x + threadIdx.x;
    if (i < BH * Dd * Dd) g_KV[i] = 0.f;
    if (i < BH * Dd)      g_Ksum[i] = 0.f;
}

#define RCH 8   // rows per chunk (4 KB smem -> can co-reside with 2 gemm CTAs)
__global__ __launch_bounds__(256) void kv_accum()
{
    const int bh = blockIdx.x;
    const int b = bh >> 3, h = bh & 7;
    const int tid = threadIdx.x;
    const int rows = Tt / KV_SPLIT;          // 512
    const size_t base = ((size_t)b * Tt + (size_t)blockIdx.y * rows) * Cc + h * Dd;

    __shared__ float sK[RCH][64];
    __shared__ float sV[RCH][64];

    const int d0 = (tid >> 4) * 4;
    const int e0 = (tid & 15) * 4;

    const int ld_r = tid >> 5;           // 0..7
    const int ld_p = (tid & 31) * 2;

    float acc[4][4];
#pragma unroll
    for (int i = 0; i < 4; i++)
#pragma unroll
        for (int j = 0; j < 4; j++) acc[i][j] = 0.f;
    float ks = 0.f;

    for (int r0 = 0; r0 < rows; r0 += RCH) {
        {
            size_t g = base + (size_t)(r0 + ld_r) * Cc + ld_p;
            float2 kf = __half22float2(*(const __half2*)(g_Kh + g));
            float2 vf = __half22float2(*(const __half2*)(g_Vh + g));
            sK[ld_r][ld_p] = kf.x; sK[ld_r][ld_p + 1] = kf.y;
            sV[ld_r][ld_p] = vf.x; sV[ld_r][ld_p + 1] = vf.y;
        }
        __syncthreads();
#pragma unroll
        for (int r = 0; r < RCH; r++) {
            float k0 = sK[r][d0], k1 = sK[r][d0 + 1], k2 = sK[r][d0 + 2], k3 = sK[r][d0 + 3];
            float v0 = sV[r][e0], v1 = sV[r][e0 + 1], v2 = sV[r][e0 + 2], v3 = sV[r][e0 + 3];
            acc[0][0] = fmaf(k0, v0, acc[0][0]); acc[0][1] = fmaf(k0, v1, acc[0][1]);
            acc[0][2] = fmaf(k0, v2, acc[0][2]); acc[0][3] = fmaf(k0, v3, acc[0][3]);
            acc[1][0] = fmaf(k1, v0, acc[1][0]); acc[1][1] = fmaf(k1, v1, acc[1][1]);
            acc[1][2] = fmaf(k1, v2, acc[1][2]); acc[1][3] = fmaf(k1, v3, acc[1][3]);
            acc[2][0] = fmaf(k2, v0, acc[2][0]); acc[2][1] = fmaf(k2, v1, acc[2][1]);
            acc[2][2] = fmaf(k2, v2, acc[2][2]); acc[2][3] = fmaf(k2, v3, acc[2][3]);
            acc[3][0] = fmaf(k3, v0, acc[3][0]); acc[3][1] = fmaf(k3, v1, acc[3][1]);
            acc[3][2] = fmaf(k3, v2, acc[3][2]); acc[3][3] = fmaf(k3, v3, acc[3][3]);
        }
        if (tid < 64) {
#pragma unroll
            for (int r = 0; r < RCH; r++) ks += sK[r][tid];
        }
        __syncthreads();
    }

    float* kvp = g_KV + (size_t)bh * Dd * Dd;
#pragma unroll
    for (int i = 0; i < 4; i++)
#pragma unroll
        for (int j = 0; j < 4; j++)
            atomicAdd(&kvp[(d0 + i) * Dd + (e0 + j)], acc[i][j]);
    if (tid < 64) atomicAdd(&g_Ksum[bh * Dd + tid], ks);
}

__global__ __launch_bounds__(256) void y_kernel()
{
    const int bh = blockIdx.y;
    const int b = bh >> 3, h = bh & 7;
    const int t0 = blockIdx.x * 64;
    const int tid = threadIdx.x;

    __shared__ float sKV[64][64];
    __shared__ float sQ[64][65];
    __shared__ float sks[64];

    const float* kvp = g_KV + (size_t)bh * Dd * Dd;
#pragma unroll
    for (int i = 0; i < 16; i++) {
        int idx = tid + i * 256;
        sKV[idx >> 6][idx & 63] = kvp[idx];
    }
    if (tid < 64) sks[tid] = g_Ksum[bh * Dd + tid];
#pragma unroll
    for (int i = 0; i < 8; i++) {
        int idx = tid + i * 256;
        int r = idx >> 5;
        int d2 = (idx & 31) * 2;
        float2 qf = __half22float2(*(const __half2*)(
            g_Qh + ((size_t)b * Tt + t0 + r) * Cc + h * Dd + d2));
        sQ[r][d2] = qf.x; sQ[r][d2 + 1] = qf.y;
    }
    __syncthreads();

    const int tok = tid >> 2;
    const int e0 = (tid & 3) * 16;

    float acc[16];
#pragma unroll
    for (int j = 0; j < 16; j++) acc[j] = 0.f;
    float nrm = 0.f;

#pragma unroll
    for (int d = 0; d < 64; d++) {
        float q = sQ[tok][d];
        nrm = fmaf(q, sks[d], nrm);
        const float4* kr = (const float4*)&sKV[d][e0];
        float4 c0 = kr[0], c1 = kr[1], c2 = kr[2], c3 = kr[3];
        acc[0]  = fmaf(q, c0.x, acc[0]);  acc[1]  = fmaf(q, c0.y, acc[1]);
        acc[2]  = fmaf(q, c0.z, acc[2]);  acc[3]  = fmaf(q, c0.w, acc[3]);
        acc[4]  = fmaf(q, c1.x, acc[4]);  acc[5]  = fmaf(q, c1.y, acc[5]);
        acc[6]  = fmaf(q, c1.z, acc[6]);  acc[7]  = fmaf(q, c1.w, acc[7]);
        acc[8]  = fmaf(q, c2.x, acc[8]);  acc[9]  = fmaf(q, c2.y, acc[9]);
        acc[10] = fmaf(q, c2.z, acc[10]); acc[11] = fmaf(q, c2.w, acc[11]);
        acc[12] = fmaf(q, c3.x, acc[12]); acc[13] = fmaf(q, c3.y, acc[13]);
        acc[14] = fmaf(q, c3.z, acc[14]); acc[15] = fmaf(q, c3.w, acc[15]);
    }

    float inv = 1.f / (nrm + 1e-6f);
    size_t ob = ((size_t)b * Tt + t0 + tok) * Cc + h * Dd + e0;
#pragma unroll
    for (int j = 0; j < 16; j += 2) {
        __half2 hv = __floats2half2_rn(acc[j] * inv, acc[j + 1] * inv);
        *(__half2*)(g_Yh + ob + j) = hv;
    }
}

// ---------------- launch ----------------
extern "C" void kernel_launch(void* const* d_in, const int* in_sizes, int n_in,
                              void* d_out, int out_size)
{
    const float* x  = (const float*)d_in[0];
    const float* Wq = (const float*)d_in[1];
    const float* bq = (const float*)d_in[2];
    const float* Wk = (const float*)d_in[3];
    const float* bk = (const float*)d_in[4];
    const float* Wv = (const float*)d_in[5];
    const float* bv = (const float*)d_in[6];
    const float* Wo = (const float*)d_in[7];
    const float* bo = (const float*)d_in[8];
    float* out = (float*)d_out;

    static __half *pXh = nullptr, *pWh, *pQh, *pKh, *pVh, *pYh;
    static cudaStream_t s1;
    static cudaEvent_t e0, eKV, eATT;
    static bool inited = false;
    if (!inited) {
        cudaGetSymbolAddress((void**)&pXh, g_Xh);
        cudaGetSymbolAddress((void**)&pWh, g_Wh);
        cudaGetSymbolAddress((void**)&pQh, g_Qh);
        cudaGetSymbolAddress((void**)&pKh, g_Kh);
        cudaGetSymbolAddress((void**)&pVh, g_Vh);
        cudaGetSymbolAddress((void**)&pYh, g_Yh);
        cudaFuncSetAttribute(gemm_kv,  cudaFuncAttributeMaxDynamicSharedMemorySize, GEMM_SMEM);
        cudaFuncSetAttribute(gemm_q,   cudaFuncAttributeMaxDynamicSharedMemorySize, GEMM_SMEM);
        cudaFuncSetAttribute(gemm_out, cudaFuncAttributeMaxDynamicSharedMemorySize, GEMM_SMEM);
        cudaStreamCreateWithFlags(&s1, cudaStreamNonBlocking);
        cudaEventCreateWithFlags(&e0,   cudaEventDisableTiming);
        cudaEventCreateWithFlags(&eKV,  cudaEventDisableTiming);
        cudaEventCreateWithFlags(&eATT, cudaEventDisableTiming);
        inited = true;
    }

    // ---- main stream: conversions ----
    {
        int n8 = NN * Cc / 8;
        cvt_f16<<<n8 / 256, 256>>>((const float4*)x, (uint4*)pXh, n8);
        int tot = 4 * Cc * Cc / 8;
        cvt_w<<<(tot + 255) / 256, 256>>>((const float4*)Wq, (const float4*)Wk,
                                          (const float4*)Wv, (const float4*)Wo, (uint4*)pWh);
    }
    cudaEventRecord(e0, 0);

    // side stream joins capture; zero_kv runs concurrent with K/V GEMM
    cudaStreamWaitEvent(s1, e0, 0);
    zero_kv<<<(BH * Dd * Dd + 255) / 256, 256, 0, s1>>>();

    // ---- K, V projections ----
    gemm_kv<<<dim3(NN / BM, 8), 256, GEMM_SMEM>>>(pXh, pWh, bk, bv, pKh, pVh);
    cudaEventRecord(eKV, 0);

    // ---- side stream: KV accumulation overlaps Q projection ----
    cudaStreamWaitEvent(s1, eKV, 0);
    kv_accum<<<dim3(BH, KV_SPLIT), 256, 0, s1>>>();
    cudaEventRecord(eATT, s1);

    // ---- Q projection (concurrent with kv_accum) ----
    gemm_q<<<dim3(NN / BM, 4), 256, GEMM_SMEM>>>(pXh, pWh, bq, pQh);

    // ---- join, then Y and output projection ----
    cudaStreamWaitEvent(0, eATT, 0);
    y_kernel<<<dim3(Tt / 64, BH), 256>>>();
    gemm_out<<<dim3(NN / BM, Cc / BN), 256, GEMM_SMEM>>>(pYh, pWh + 3 * (size_t)Cc * Cc, bo, out);
}

// round 11
// speedup vs baseline: 1.6927x; 1.6927x over previous
#include <cuda_runtime.h>
#include <cuda_fp16.h>
#include <math.h>
#include <stdint.h>

// ---------------- Problem constants ----------------
#define Bb 8
#define Tt 8192
#define Cc 512
#define Hh 8
#define Dd 64
#define NN (Bb*Tt)         // 65536 tokens
#define BH (Bb*Hh)         // 64
#define KV_SPLIT 16

// ---------------- Scratch (device globals) ----------------
__device__ __half g_Xh[(size_t)NN*Cc];
__device__ __half g_Wh[(size_t)4*Cc*Cc];
__device__ __half g_Qh[(size_t)NN*Cc];
__device__ __half g_Kh[(size_t)NN*Cc];
__device__ __half g_Vh[(size_t)NN*Cc];
__device__ __half g_Yh[(size_t)NN*Cc];
__device__ float  g_KVp[(size_t)KV_SPLIT*BH*Dd*Dd];   // partial KV sums
__device__ float  g_Ksp[(size_t)KV_SPLIT*BH*Dd];      // partial Ksum
__device__ __half g_KVt[(size_t)BH*Dd*Dd];            // KV^T (e-major) fp16
__device__ float  g_Ksum[(size_t)BH*Dd];

// ---------------- helpers ----------------
__device__ __forceinline__ uint32_t smem_u32(const void* p) {
    uint32_t a;
    asm("{ .reg .u64 t; cvta.to.shared.u64 t, %1; cvt.u32.u64 %0, t; }" : "=r"(a) : "l"(p));
    return a;
}
#define CP_ASYNC16(dst, src) \
    asm volatile("cp.async.cg.shared.global [%0], [%1], 16;" :: "r"(dst), "l"(src) : "memory")
#define CP_COMMIT() asm volatile("cp.async.commit_group;" ::: "memory")
#define CP_WAIT(n)  asm volatile("cp.async.wait_group %0;" :: "n"(n) : "memory")

__device__ __forceinline__ void ldsm_x4(uint32_t* r, uint32_t addr) {
    asm volatile("ldmatrix.sync.aligned.m8n8.x4.shared.b16 {%0,%1,%2,%3}, [%4];"
                 : "=r"(r[0]), "=r"(r[1]), "=r"(r[2]), "=r"(r[3]) : "r"(addr));
}
__device__ __forceinline__ void mma_f16(float* c, const uint32_t* a, uint32_t b0, uint32_t b1) {
    asm volatile("mma.sync.aligned.m16n8k16.row.col.f32.f16.f16.f32 "
                 "{%0,%1,%2,%3},{%4,%5,%6,%7},{%8,%9},{%0,%1,%2,%3};"
                 : "+f"(c[0]), "+f"(c[1]), "+f"(c[2]), "+f"(c[3])
                 : "r"(a[0]), "r"(a[1]), "r"(a[2]), "r"(a[3]), "r"(b0), "r"(b1));
}

// ---------------- GEMM config (fp16, 128x128 CTA, 8 warps of 64x32) ----------------
#define BM 128
#define BN 128
#define BKH 64
#define NKH (Cc / BKH)
#define ASTRH 72
#define TILEH (BM * ASTRH)
#define STAGEH (2 * TILEH)
#define NSTG 3
#define GEMM_SMEM (NSTG * STAGEH * 2)   // 110592 bytes

__device__ __forceinline__ void gemm_core(
    const __half* __restrict__ A, const __half* __restrict__ B,
    int m0, int n0, __half* smh, float acc[4][4][4])
{
    const int tid = threadIdx.x;
    const int wid = tid >> 5;
    const int lane = tid & 31;
    const int m_warp = (wid >> 2) * 64;
    const int n_warp = (wid & 3) * 32;

    const int g8 = lane >> 3;
    const int r8 = lane & 7;
    const int a_row_l = r8 + (g8 & 1) * 8;
    const int a_kb    = (g8 >> 1) * 16;
    const int b_row_l = r8 + (g8 >> 1) * 8;
    const int b_kb    = (g8 & 1) * 16;

    const uint32_t smb = smem_u32(smh);

#pragma unroll
    for (int i = 0; i < 4; i++)
#pragma unroll
        for (int j = 0; j < 4; j++)
#pragma unroll
            for (int k = 0; k < 4; k++) acc[i][j][k] = 0.f;

    auto load_stage = [&](int kc, int s) {
        const __half* gA = A + (size_t)m0 * Cc + kc * BKH;
        const __half* gB = B + (size_t)n0 * Cc + kc * BKH;
        uint32_t dA = smb + (uint32_t)(s * STAGEH) * 2;
        uint32_t dB = dA + (uint32_t)TILEH * 2;
#pragma unroll
        for (int i = 0; i < 4; i++) {
            int idx = tid + i * 256;
            int row = idx >> 3;
            int c8 = idx & 7;
            CP_ASYNC16(dA + (uint32_t)(row * ASTRH + c8 * 8) * 2, gA + (size_t)row * Cc + c8 * 8);
        }
#pragma unroll
        for (int i = 0; i < 4; i++) {
            int idx = tid + i * 256;
            int row = idx >> 3;
            int c8 = idx & 7;
            CP_ASYNC16(dB + (uint32_t)(row * ASTRH + c8 * 8) * 2, gB + (size_t)row * Cc + c8 * 8);
        }
        CP_COMMIT();
    };

    load_stage(0, 0);
    load_stage(1, 1);

    for (int kt = 0; kt < NKH; kt++) {
        if (kt < NKH - 1) CP_WAIT(1); else CP_WAIT(0);
        __syncthreads();
        if (kt + 2 < NKH) load_stage(kt + 2, (kt + 2) % 3);

        const int s = kt % 3;
        const uint32_t aB = smb + (uint32_t)(s * STAGEH) * 2
                          + (uint32_t)((m_warp + a_row_l) * ASTRH) * 2 + a_kb;
        const uint32_t bB = smb + (uint32_t)(s * STAGEH + TILEH) * 2
                          + (uint32_t)((n_warp + b_row_l) * ASTRH) * 2 + b_kb;

#pragma unroll
        for (int ks = 0; ks < 4; ks++) {
            uint32_t af[4][4];
#pragma unroll
            for (int mi = 0; mi < 4; mi++)
                ldsm_x4(af[mi], aB + (uint32_t)(mi * 16 * ASTRH) * 2 + ks * 32);
            uint32_t bf[2][4];
#pragma unroll
            for (int p = 0; p < 2; p++)
                ldsm_x4(bf[p], bB + (uint32_t)(p * 16 * ASTRH) * 2 + ks * 32);
#pragma unroll
            for (int mi = 0; mi < 4; mi++) {
#pragma unroll
                for (int p = 0; p < 2; p++) {
                    mma_f16(acc[mi][p * 2 + 0], af[mi], bf[p][0], bf[p][1]);
                    mma_f16(acc[mi][p * 2 + 1], af[mi], bf[p][2], bf[p][3]);
                }
            }
        }
    }
}

__device__ __forceinline__ void epilogue_h(
    float acc[4][4][4], const float* bias, __half* outp, int m0, int n0, int act)
{
    const int tid = threadIdx.x;
    const int wid = tid >> 5;
    const int lane = tid & 31;
    const int m_warp = (wid >> 2) * 64;
    const int n_warp = (wid & 3) * 32;
    const int r_lo = lane >> 2;
    const int c_off = (lane & 3) * 2;
#pragma unroll
    for (int mi = 0; mi < 4; mi++) {
#pragma unroll
        for (int nj = 0; nj < 4; nj++) {
            int col = n0 + n_warp + nj * 8 + c_off;
            float b0 = bias[col], b1 = bias[col + 1];
#pragma unroll
            for (int half_ = 0; half_ < 2; half_++) {
                int row = m0 + m_warp + mi * 16 + r_lo + half_ * 8;
                float v0 = acc[mi][nj][half_ * 2 + 0] + b0;
                float v1 = acc[mi][nj][half_ * 2 + 1] + b1;
                if (act) {
                    v0 = (v0 > 0.f) ? v0 + 1.f : expf(v0);
                    v1 = (v1 > 0.f) ? v1 + 1.f : expf(v1);
                }
                __half2 hv = __floats2half2_rn(v0, v1);
                *(__half2*)(outp + (size_t)row * Cc + col) = hv;
            }
        }
    }
}

// Fused QKV projection: grid (NN/BM, 12). Segment = by>>2: 0=Q,1=K,2=V.
__global__ __launch_bounds__(256, 2)
void gemm_qkv(const __half* __restrict__ X, const __half* __restrict__ W,
              const float* __restrict__ bq, const float* __restrict__ bk,
              const float* __restrict__ bv,
              __half* __restrict__ Q, __half* __restrict__ K, __half* __restrict__ V)
{
    extern __shared__ __half smh[];
    const int seg = blockIdx.y >> 2;
    const int n0 = (blockIdx.y & 3) * BN;
    const int m0 = blockIdx.x * BM;

    const __half* B = W + (size_t)seg * Cc * Cc;
    const float* bias = (seg == 0) ? bq : (seg == 1) ? bk : bv;
    __half* outp = (seg == 0) ? Q : (seg == 1) ? K : V;
    const int act = (seg < 2);

    float acc[4][4][4];
    gemm_core(X, B, m0, n0, smh, acc);
    epilogue_h(acc, bias, outp, m0, n0, act);
}

// Output projection: f32 store, no activation.
__global__ __launch_bounds__(256, 2)
void gemm_out(const __half* __restrict__ Y, const __half* __restrict__ W,
              const float* __restrict__ bias, float* __restrict__ outp)
{
    extern __shared__ __half smh[];
    const int m0 = blockIdx.x * BM;
    const int n0 = blockIdx.y * BN;

    float acc[4][4][4];
    gemm_core(Y, W, m0, n0, smh, acc);

    const int tid = threadIdx.x;
    const int wid = tid >> 5;
    const int lane = tid & 31;
    const int m_warp = (wid >> 2) * 64;
    const int n_warp = (wid & 3) * 32;
    const int r_lo = lane >> 2;
    const int c_off = (lane & 3) * 2;
#pragma unroll
    for (int mi = 0; mi < 4; mi++) {
#pragma unroll
        for (int nj = 0; nj < 4; nj++) {
            int col = n0 + n_warp + nj * 8 + c_off;
            float b0 = bias[col], b1 = bias[col + 1];
#pragma unroll
            for (int half_ = 0; half_ < 2; half_++) {
                int row = m0 + m_warp + mi * 16 + r_lo + half_ * 8;
                float v0 = acc[mi][nj][half_ * 2 + 0] + b0;
                float v1 = acc[mi][nj][half_ * 2 + 1] + b1;
                *(float2*)(outp + (size_t)row * Cc + col) = make_float2(v0, v1);
            }
        }
    }
}

// ---------------- f32 -> f16 conversions ----------------
__global__ __launch_bounds__(256) void cvt_f16(const float4* __restrict__ src,
                                               uint4* __restrict__ dst, int n8)
{
    int i = blockIdx.x * blockDim.x + threadIdx.x;
    if (i < n8) {
        float4 a = src[2 * i], b = src[2 * i + 1];
        __half2 h0 = __floats2half2_rn(a.x, a.y);
        __half2 h1 = __floats2half2_rn(a.z, a.w);
        __half2 h2 = __floats2half2_rn(b.x, b.y);
        __half2 h3 = __floats2half2_rn(b.z, b.w);
        uint4 o;
        o.x = *(uint32_t*)&h0; o.y = *(uint32_t*)&h1;
        o.z = *(uint32_t*)&h2; o.w = *(uint32_t*)&h3;
        dst[i] = o;
    }
}

__global__ __launch_bounds__(256) void cvt_w(
    const float4* __restrict__ w0, const float4* __restrict__ w1,
    const float4* __restrict__ w2, const float4* __restrict__ w3,
    uint4* __restrict__ dst)
{
    const int w8 = Cc * Cc / 8;
    int i = blockIdx.x * blockDim.x + threadIdx.x;
    if (i >= 4 * w8) return;
    int seg = i / w8, j = i - seg * w8;
    const float4* src = (seg == 0) ? w0 : (seg == 1) ? w1 : (seg == 2) ? w2 : w3;
    float4 a = src[2 * j], b = src[2 * j + 1];
    __half2 h0 = __floats2half2_rn(a.x, a.y);
    __half2 h1 = __floats2half2_rn(a.z, a.w);
    __half2 h2 = __floats2half2_rn(b.x, b.y);
    __half2 h3 = __floats2half2_rn(b.z, b.w);
    uint4 o;
    o.x = *(uint32_t*)&h0; o.y = *(uint32_t*)&h1;
    o.z = *(uint32_t*)&h2; o.w = *(uint32_t*)&h3;
    dst[i] = o;
}

// ---------------- attention-side kernels ----------------
#define RCH 16   // rows per chunk
__global__ __launch_bounds__(256) void kv_accum()
{
    const int bh = blockIdx.x;
    const int b = bh >> 3, h = bh & 7;
    const int tid = threadIdx.x;
    const int rows = Tt / KV_SPLIT;          // 512
    const size_t base = ((size_t)b * Tt + (size_t)blockIdx.y * rows) * Cc + h * Dd;

    __shared__ float sK[RCH][64];
    __shared__ float sV[RCH][64];

    const int d0 = (tid >> 4) * 4;
    const int e0 = (tid & 15) * 4;

    float acc[4][4];
#pragma unroll
    for (int i = 0; i < 4; i++)
#pragma unroll
        for (int j = 0; j < 4; j++) acc[i][j] = 0.f;
    float ks = 0.f;

    for (int r0 = 0; r0 < rows; r0 += RCH) {
#pragma unroll
        for (int i = 0; i < RCH * 32 / 256; i++) {
            int lin = tid + i * 256;
            int rr = lin >> 5;
            int pp = (lin & 31) * 2;
            size_t g = base + (size_t)(r0 + rr) * Cc + pp;
            float2 kf = __half22float2(*(const __half2*)(g_Kh + g));
            float2 vf = __half22float2(*(const __half2*)(g_Vh + g));
            sK[rr][pp] = kf.x; sK[rr][pp + 1] = kf.y;
            sV[rr][pp] = vf.x; sV[rr][pp + 1] = vf.y;
        }
        __syncthreads();
#pragma unroll
        for (int r = 0; r < RCH; r++) {
            float k0 = sK[r][d0], k1 = sK[r][d0 + 1], k2 = sK[r][d0 + 2], k3 = sK[r][d0 + 3];
            float v0 = sV[r][e0], v1 = sV[r][e0 + 1], v2 = sV[r][e0 + 2], v3 = sV[r][e0 + 3];
            acc[0][0] = fmaf(k0, v0, acc[0][0]); acc[0][1] = fmaf(k0, v1, acc[0][1]);
            acc[0][2] = fmaf(k0, v2, acc[0][2]); acc[0][3] = fmaf(k0, v3, acc[0][3]);
            acc[1][0] = fmaf(k1, v0, acc[1][0]); acc[1][1] = fmaf(k1, v1, acc[1][1]);
            acc[1][2] = fmaf(k1, v2, acc[1][2]); acc[1][3] = fmaf(k1, v3, acc[1][3]);
            acc[2][0] = fmaf(k2, v0, acc[2][0]); acc[2][1] = fmaf(k2, v1, acc[2][1]);
            acc[2][2] = fmaf(k2, v2, acc[2][2]); acc[2][3] = fmaf(k2, v3, acc[2][3]);
            acc[3][0] = fmaf(k3, v0, acc[3][0]); acc[3][1] = fmaf(k3, v1, acc[3][1]);
            acc[3][2] = fmaf(k3, v2, acc[3][2]); acc[3][3] = fmaf(k3, v3, acc[3][3]);
        }
        if (tid < 64) {
#pragma unroll
            for (int r = 0; r < RCH; r++) ks += sK[r][tid];
        }
        __syncthreads();
    }

    // partial stores (no atomics): g_KVp[split][bh][d][e]
    float* kvp = g_KVp + ((size_t)blockIdx.y * BH + bh) * (Dd * Dd);
#pragma unroll
    for (int i = 0; i < 4; i++)
        *(float4*)(kvp + (d0 + i) * Dd + e0) =
            make_float4(acc[i][0], acc[i][1], acc[i][2], acc[i][3]);
    if (tid < 64)
        g_Ksp[((size_t)blockIdx.y * BH + bh) * Dd + tid] = ks;
}

// Reduce partials -> Ksum (fp32) and KVt = KV^T (fp16, e-major). grid = BH.
__global__ __launch_bounds__(256) void kv_reduce()
{
    const int bh = blockIdx.x;
    const int tid = threadIdx.x;
    __shared__ float sT[64][65];

#pragma unroll
    for (int j = 0; j < 16; j++) {
        int idx = j * 256 + tid;             // d*64+e
        float s = 0.f;
#pragma unroll
        for (int p = 0; p < KV_SPLIT; p++)
            s += g_KVp[((size_t)p * BH + bh) * (Dd * Dd) + idx];
        sT[idx >> 6][idx & 63] = s;
    }
    if (tid < 64) {
        float s = 0.f;
#pragma unroll
        for (int p = 0; p < KV_SPLIT; p++)
            s += g_Ksp[((size_t)p * BH + bh) * Dd + tid];
        g_Ksum[bh * Dd + tid] = s;
    }
    __syncthreads();

    // transposed write: KVt[e][d] = KV[d][e]
#pragma unroll
    for (int j = 0; j < 16; j++) {
        int idx = j * 256 + tid;             // e*64+d (output order)
        int e = idx >> 6, d = idx & 63;
        g_KVt[(size_t)bh * (Dd * Dd) + idx] = __float2half(sT[d][e]);
    }
}

// ---------------- tensor-core Y kernel ----------------
// Y[t][e] = (Q[t,:] . KVt[e,:]) / (Q[t,:] . Ksum + 1e-6)
// grid (Tt/64, BH), 128 threads (4 warps, each 16 tokens x 64 e).
#define YSTR 72
__global__ __launch_bounds__(128) void y_mma()
{
    const int bh = blockIdx.y;
    const int b = bh >> 3, h = bh & 7;
    const int t0 = blockIdx.x * 64;
    const int tid = threadIdx.x;
    const int wid = tid >> 5;
    const int lane = tid & 31;

    __shared__ __align__(16) __half sQ[64 * YSTR];
    __shared__ __align__(16) __half sB[64 * YSTR];
    __shared__ float sKs[64];
    __shared__ float sInv[64];

    // load Q tile (64 x 64 halves) and KVt tile, 512 uint4 each, 4/thread
#pragma unroll
    for (int i = 0; i < 4; i++) {
        int idx = tid + i * 128;             // 0..511
        int row = idx >> 3;
        int c8 = idx & 7;
        *(uint4*)(sQ + row * YSTR + c8 * 8) =
            *(const uint4*)(g_Qh + ((size_t)b * Tt + t0 + row) * Cc + h * Dd + c8 * 8);
        *(uint4*)(sB + row * YSTR + c8 * 8) =
            *(const uint4*)(g_KVt + (size_t)bh * (Dd * Dd) + (size_t)row * Dd + c8 * 8);
    }
    if (tid < 64) sKs[tid] = g_Ksum[bh * Dd + tid];
    __syncthreads();

    // normalizer (threads 0..63, one token each)
    if (tid < 64) {
        float s = 0.f;
#pragma unroll
        for (int d = 0; d < 64; d++)
            s = fmaf(__half2float(sQ[tid * YSTR + d]), sKs[d], s);
        sInv[tid] = 1.f / (s + 1e-6f);
    }

    const int g8 = lane >> 3;
    const int r8 = lane & 7;
    const int a_row_l = r8 + (g8 & 1) * 8;
    const int a_kb    = (g8 >> 1) * 16;
    const int b_row_l = r8 + (g8 >> 1) * 8;
    const int b_kb    = (g8 & 1) * 16;

    const uint32_t qB = smem_u32(sQ) + (uint32_t)((wid * 16 + a_row_l) * YSTR) * 2 + a_kb;
    const uint32_t bB = smem_u32(sB) + (uint32_t)(b_row_l * YSTR) * 2 + b_kb;

    float acc[8][4];
#pragma unroll
    for (int j = 0; j < 8; j++)
#pragma unroll
        for (int k = 0; k < 4; k++) acc[j][k] = 0.f;

    __syncthreads();   // ensure sInv + tiles ready for all warps

#pragma unroll
    for (int ks = 0; ks < 4; ks++) {         // k = d, 4 x k16
        uint32_t af[4];
        ldsm_x4(af, qB + ks * 32);
        uint32_t bf[4][4];
#pragma unroll
        for (int p = 0; p < 4; p++)
            ldsm_x4(bf[p], bB + (uint32_t)(p * 16 * YSTR) * 2 + ks * 32);
#pragma unroll
        for (int p = 0; p < 4; p++) {
            mma_f16(acc[p * 2 + 0], af, bf[p][0], bf[p][1]);
            mma_f16(acc[p * 2 + 1], af, bf[p][2], bf[p][3]);
        }
    }

    // epilogue: divide by normalizer, write fp16 Y
    const int r_lo = lane >> 2;
    const int c_off = (lane & 3) * 2;
#pragma unroll
    for (int nj = 0; nj < 8; nj++) {
        int col = nj * 8 + c_off;
#pragma unroll
        for (int half_ = 0; half_ < 2; half_++) {
            int tok = wid * 16 + r_lo + half_ * 8;
            float inv = sInv[tok];
            __half2 hv = __floats2half2_rn(acc[nj][half_ * 2 + 0] * inv,
                                           acc[nj][half_ * 2 + 1] * inv);
            *(__half2*)(g_Yh + ((size_t)b * Tt + t0 + tok) * Cc + h * Dd + col) = hv;
        }
    }
}

// ---------------- launch ----------------
extern "C" void kernel_launch(void* const* d_in, const int* in_sizes, int n_in,
                              void* d_out, int out_size)
{
    const float* x  = (const float*)d_in[0];
    const float* Wq = (const float*)d_in[1];
    const float* bq = (const float*)d_in[2];
    const float* Wk = (const float*)d_in[3];
    const float* bk = (const float*)d_in[4];
    const float* Wv = (const float*)d_in[5];
    const float* bv = (const float*)d_in[6];
    const float* Wo = (const float*)d_in[7];
    const float* bo = (const float*)d_in[8];
    float* out = (float*)d_out;

    static __half *pXh = nullptr, *pWh, *pQh, *pKh, *pVh, *pYh;
    static bool inited = false;
    if (!inited) {
        cudaGetSymbolAddress((void**)&pXh, g_Xh);
        cudaGetSymbolAddress((void**)&pWh, g_Wh);
        cudaGetSymbolAddress((void**)&pQh, g_Qh);
        cudaGetSymbolAddress((void**)&pKh, g_Kh);
        cudaGetSymbolAddress((void**)&pVh, g_Vh);
        cudaGetSymbolAddress((void**)&pYh, g_Yh);
        cudaFuncSetAttribute(gemm_qkv, cudaFuncAttributeMaxDynamicSharedMemorySize, GEMM_SMEM);
        cudaFuncSetAttribute(gemm_out, cudaFuncAttributeMaxDynamicSharedMemorySize, GEMM_SMEM);
        inited = true;
    }

    // f32 -> f16 conversions
    {
        int n8 = NN * Cc / 8;
        cvt_f16<<<n8 / 256, 256>>>((const float4*)x, (uint4*)pXh, n8);
        int tot = 4 * Cc * Cc / 8;
        cvt_w<<<(tot + 255) / 256, 256>>>((const float4*)Wq, (const float4*)Wk,
                                          (const float4*)Wv, (const float4*)Wo, (uint4*)pWh);
    }

    // Fused Q/K/V projections
    gemm_qkv<<<dim3(NN / BM, 12), 256, GEMM_SMEM>>>(pXh, pWh, bq, bk, bv, pQh, pKh, pVh);

    // KV accumulation (partials) -> reduce -> tensor-core Y
    kv_accum<<<dim3(BH, KV_SPLIT), 256>>>();
    kv_reduce<<<BH, 256>>>();
    y_mma<<<dim3(Tt / 64, BH), 128>>>();

    // Output projection
    gemm_out<<<dim3(NN / BM, Cc / BN), 256, GEMM_SMEM>>>(pYh, pWh + 3 * (size_t)Cc * Cc, bo, out);
}

// round 12
// speedup vs baseline: 1.9102x; 1.1285x over previous
#include <cuda_runtime.h>
#include <cuda_fp16.h>
#include <math.h>
#include <stdint.h>

// ---------------- Problem constants ----------------
#define Bb 8
#define Tt 8192
#define Cc 512
#define Hh 8
#define Dd 64
#define NN (Bb*Tt)         // 65536 tokens
#define BH (Bb*Hh)         // 64
#define KV_SPLIT 16
#define KVROWS (Tt / KV_SPLIT)   // 512

// ---------------- Scratch (device globals) ----------------
__device__ __half g_Xh[(size_t)NN*Cc];
__device__ __half g_Wh[(size_t)4*Cc*Cc];
__device__ __half g_Qh[(size_t)NN*Cc];
__device__ __half g_Kh[(size_t)NN*Cc];
__device__ __half g_Vh[(size_t)NN*Cc];
__device__ __half g_Yh[(size_t)NN*Cc];
__device__ float  g_KVp[(size_t)KV_SPLIT*BH*Dd*Dd];   // partial KVt sums ([e][d] order)
__device__ float  g_Ksp[(size_t)KV_SPLIT*BH*Dd];      // partial Ksum
__device__ __half g_KVt[(size_t)BH*Dd*Dd];            // KV^T (e-major) fp16
__device__ float  g_Ksum[(size_t)BH*Dd];

// ---------------- helpers ----------------
__device__ __forceinline__ uint32_t smem_u32(const void* p) {
    uint32_t a;
    asm("{ .reg .u64 t; cvta.to.shared.u64 t, %1; cvt.u32.u64 %0, t; }" : "=r"(a) : "l"(p));
    return a;
}
#define CP_ASYNC16(dst, src) \
    asm volatile("cp.async.cg.shared.global [%0], [%1], 16;" :: "r"(dst), "l"(src) : "memory")
#define CP_COMMIT() asm volatile("cp.async.commit_group;" ::: "memory")
#define CP_WAIT(n)  asm volatile("cp.async.wait_group %0;" :: "n"(n) : "memory")

__device__ __forceinline__ void ldsm_x4(uint32_t* r, uint32_t addr) {
    asm volatile("ldmatrix.sync.aligned.m8n8.x4.shared.b16 {%0,%1,%2,%3}, [%4];"
                 : "=r"(r[0]), "=r"(r[1]), "=r"(r[2]), "=r"(r[3]) : "r"(addr));
}
__device__ __forceinline__ void ldsm_x4_t(uint32_t* r, uint32_t addr) {
    asm volatile("ldmatrix.sync.aligned.m8n8.x4.trans.shared.b16 {%0,%1,%2,%3}, [%4];"
                 : "=r"(r[0]), "=r"(r[1]), "=r"(r[2]), "=r"(r[3]) : "r"(addr));
}
__device__ __forceinline__ void mma_f16(float* c, const uint32_t* a, uint32_t b0, uint32_t b1) {
    asm volatile("mma.sync.aligned.m16n8k16.row.col.f32.f16.f16.f32 "
                 "{%0,%1,%2,%3},{%4,%5,%6,%7},{%8,%9},{%0,%1,%2,%3};"
                 : "+f"(c[0]), "+f"(c[1]), "+f"(c[2]), "+f"(c[3])
                 : "r"(a[0]), "r"(a[1]), "r"(a[2]), "r"(a[3]), "r"(b0), "r"(b1));
}

// ---------------- GEMM config (fp16, 128x128 CTA, 8 warps of 64x32) ----------------
#define BM 128
#define BN 128
#define BKH 64
#define NKH (Cc / BKH)
#define ASTRH 72
#define TILEH (BM * ASTRH)
#define STAGEH (2 * TILEH)
#define NSTG 3
#define GEMM_SMEM (NSTG * STAGEH * 2)   // 110592 bytes

__device__ __forceinline__ void gemm_core(
    const __half* __restrict__ A, const __half* __restrict__ B,
    int m0, int n0, __half* smh, float acc[4][4][4])
{
    const int tid = threadIdx.x;
    const int wid = tid >> 5;
    const int lane = tid & 31;
    const int m_warp = (wid >> 2) * 64;
    const int n_warp = (wid & 3) * 32;

    const int g8 = lane >> 3;
    const int r8 = lane & 7;
    const int a_row_l = r8 + (g8 & 1) * 8;
    const int a_kb    = (g8 >> 1) * 16;
    const int b_row_l = r8 + (g8 >> 1) * 8;
    const int b_kb    = (g8 & 1) * 16;

    const uint32_t smb = smem_u32(smh);

#pragma unroll
    for (int i = 0; i < 4; i++)
#pragma unroll
        for (int j = 0; j < 4; j++)
#pragma unroll
            for (int k = 0; k < 4; k++) acc[i][j][k] = 0.f;

    auto load_stage = [&](int kc, int s) {
        const __half* gA = A + (size_t)m0 * Cc + kc * BKH;
        const __half* gB = B + (size_t)n0 * Cc + kc * BKH;
        uint32_t dA = smb + (uint32_t)(s * STAGEH) * 2;
        uint32_t dB = dA + (uint32_t)TILEH * 2;
#pragma unroll
        for (int i = 0; i < 4; i++) {
            int idx = tid + i * 256;
            int row = idx >> 3;
            int c8 = idx & 7;
            CP_ASYNC16(dA + (uint32_t)(row * ASTRH + c8 * 8) * 2, gA + (size_t)row * Cc + c8 * 8);
        }
#pragma unroll
        for (int i = 0; i < 4; i++) {
            int idx = tid + i * 256;
            int row = idx >> 3;
            int c8 = idx & 7;
            CP_ASYNC16(dB + (uint32_t)(row * ASTRH + c8 * 8) * 2, gB + (size_t)row * Cc + c8 * 8);
        }
        CP_COMMIT();
    };

    load_stage(0, 0);
    load_stage(1, 1);

    for (int kt = 0; kt < NKH; kt++) {
        if (kt < NKH - 1) CP_WAIT(1); else CP_WAIT(0);
        __syncthreads();
        if (kt + 2 < NKH) load_stage(kt + 2, (kt + 2) % 3);

        const int s = kt % 3;
        const uint32_t aB = smb + (uint32_t)(s * STAGEH) * 2
                          + (uint32_t)((m_warp + a_row_l) * ASTRH) * 2 + a_kb;
        const uint32_t bB = smb + (uint32_t)(s * STAGEH + TILEH) * 2
                          + (uint32_t)((n_warp + b_row_l) * ASTRH) * 2 + b_kb;

#pragma unroll
        for (int ks = 0; ks < 4; ks++) {
            uint32_t af[4][4];
#pragma unroll
            for (int mi = 0; mi < 4; mi++)
                ldsm_x4(af[mi], aB + (uint32_t)(mi * 16 * ASTRH) * 2 + ks * 32);
            uint32_t bf[2][4];
#pragma unroll
            for (int p = 0; p < 2; p++)
                ldsm_x4(bf[p], bB + (uint32_t)(p * 16 * ASTRH) * 2 + ks * 32);
#pragma unroll
            for (int mi = 0; mi < 4; mi++) {
#pragma unroll
                for (int p = 0; p < 2; p++) {
                    mma_f16(acc[mi][p * 2 + 0], af[mi], bf[p][0], bf[p][1]);
                    mma_f16(acc[mi][p * 2 + 1], af[mi], bf[p][2], bf[p][3]);
                }
            }
        }
    }
}

__device__ __forceinline__ void epilogue_h(
    float acc[4][4][4], const float* bias, __half* outp, int m0, int n0, int act)
{
    const int tid = threadIdx.x;
    const int wid = tid >> 5;
    const int lane = tid & 31;
    const int m_warp = (wid >> 2) * 64;
    const int n_warp = (wid & 3) * 32;
    const int r_lo = lane >> 2;
    const int c_off = (lane & 3) * 2;
#pragma unroll
    for (int mi = 0; mi < 4; mi++) {
#pragma unroll
        for (int nj = 0; nj < 4; nj++) {
            int col = n0 + n_warp + nj * 8 + c_off;
            float b0 = bias[col], b1 = bias[col + 1];
#pragma unroll
            for (int half_ = 0; half_ < 2; half_++) {
                int row = m0 + m_warp + mi * 16 + r_lo + half_ * 8;
                float v0 = acc[mi][nj][half_ * 2 + 0] + b0;
                float v1 = acc[mi][nj][half_ * 2 + 1] + b1;
                if (act) {
                    v0 = (v0 > 0.f) ? v0 + 1.f : expf(v0);
                    v1 = (v1 > 0.f) ? v1 + 1.f : expf(v1);
                }
                __half2 hv = __floats2half2_rn(v0, v1);
                *(__half2*)(outp + (size_t)row * Cc + col) = hv;
            }
        }
    }
}

// Fused QKV projection: grid (NN/BM, 12). Segment = by>>2: 0=Q,1=K,2=V.
__global__ __launch_bounds__(256, 2)
void gemm_qkv(const __half* __restrict__ X, const __half* __restrict__ W,
              const float* __restrict__ bq, const float* __restrict__ bk,
              const float* __restrict__ bv,
              __half* __restrict__ Q, __half* __restrict__ K, __half* __restrict__ V)
{
    extern __shared__ __half smh[];
    const int seg = blockIdx.y >> 2;
    const int n0 = (blockIdx.y & 3) * BN;
    const int m0 = blockIdx.x * BM;

    const __half* B = W + (size_t)seg * Cc * Cc;
    const float* bias = (seg == 0) ? bq : (seg == 1) ? bk : bv;
    __half* outp = (seg == 0) ? Q : (seg == 1) ? K : V;
    const int act = (seg < 2);

    float acc[4][4][4];
    gemm_core(X, B, m0, n0, smh, acc);
    epilogue_h(acc, bias, outp, m0, n0, act);
}

// Output projection: f32 store, no activation.
__global__ __launch_bounds__(256, 2)
void gemm_out(const __half* __restrict__ Y, const __half* __restrict__ W,
              const float* __restrict__ bias, float* __restrict__ outp)
{
    extern __shared__ __half smh[];
    const int m0 = blockIdx.x * BM;
    const int n0 = blockIdx.y * BN;

    float acc[4][4][4];
    gemm_core(Y, W, m0, n0, smh, acc);

    const int tid = threadIdx.x;
    const int wid = tid >> 5;
    const int lane = tid & 31;
    const int m_warp = (wid >> 2) * 64;
    const int n_warp = (wid & 3) * 32;
    const int r_lo = lane >> 2;
    const int c_off = (lane & 3) * 2;
#pragma unroll
    for (int mi = 0; mi < 4; mi++) {
#pragma unroll
        for (int nj = 0; nj < 4; nj++) {
            int col = n0 + n_warp + nj * 8 + c_off;
            float b0 = bias[col], b1 = bias[col + 1];
#pragma unroll
            for (int half_ = 0; half_ < 2; half_++) {
                int row = m0 + m_warp + mi * 16 + r_lo + half_ * 8;
                float v0 = acc[mi][nj][half_ * 2 + 0] + b0;
                float v1 = acc[mi][nj][half_ * 2 + 1] + b1;
                *(float2*)(outp + (size_t)row * Cc + col) = make_float2(v0, v1);
            }
        }
    }
}

// ---------------- f32 -> f16 conversions ----------------
__global__ __launch_bounds__(256) void cvt_f16(const float4* __restrict__ src,
                                               uint4* __restrict__ dst, int n8)
{
    int i = blockIdx.x * blockDim.x + threadIdx.x;
    if (i < n8) {
        float4 a = src[2 * i], b = src[2 * i + 1];
        __half2 h0 = __floats2half2_rn(a.x, a.y);
        __half2 h1 = __floats2half2_rn(a.z, a.w);
        __half2 h2 = __floats2half2_rn(b.x, b.y);
        __half2 h3 = __floats2half2_rn(b.z, b.w);
        uint4 o;
        o.x = *(uint32_t*)&h0; o.y = *(uint32_t*)&h1;
        o.z = *(uint32_t*)&h2; o.w = *(uint32_t*)&h3;
        dst[i] = o;
    }
}

__global__ __launch_bounds__(256) void cvt_w(
    const float4* __restrict__ w0, const float4* __restrict__ w1,
    const float4* __restrict__ w2, const float4* __restrict__ w3,
    uint4* __restrict__ dst)
{
    const int w8 = Cc * Cc / 8;
    int i = blockIdx.x * blockDim.x + threadIdx.x;
    if (i >= 4 * w8) return;
    int seg = i / w8, j = i - seg * w8;
    const float4* src = (seg == 0) ? w0 : (seg == 1) ? w1 : (seg == 2) ? w2 : w3;
    float4 a = src[2 * j], b = src[2 * j + 1];
    __half2 h0 = __floats2half2_rn(a.x, a.y);
    __half2 h1 = __floats2half2_rn(a.z, a.w);
    __half2 h2 = __floats2half2_rn(b.x, b.y);
    __half2 h3 = __floats2half2_rn(b.z, b.w);
    uint4 o;
    o.x = *(uint32_t*)&h0; o.y = *(uint32_t*)&h1;
    o.z = *(uint32_t*)&h2; o.w = *(uint32_t*)&h3;
    dst[i] = o;
}

// ---------------- tensor-core KV accumulation ----------------
// KVt_partial[e][d] = sum_t V[t][e] * K[t][d]  over this split's 512 rows.
// A = V^T (m=e, k=t) via ldmatrix.trans; B = K^T (n=d, k=t) via ldmatrix.trans.
// grid (BH, KV_SPLIT), 128 threads (4 warps; warp w covers e rows w*16..+15).
#define KSTR 72
__global__ __launch_bounds__(128) void kv_mma()
{
    const int bh = blockIdx.x;
    const int b = bh >> 3, h = bh & 7;
    const int split = blockIdx.y;
    const int tid = threadIdx.x;
    const int wid = tid >> 5;
    const int lane = tid & 31;
    const size_t base = ((size_t)b * Tt + (size_t)split * KVROWS) * Cc + h * Dd;

    __shared__ __align__(16) __half sK[64 * KSTR];
    __shared__ __align__(16) __half sV[64 * KSTR];

    const int g8 = lane >> 3;
    const int r8 = lane & 7;
    // trans-A (V^T): quads (R,C)=(0,0),(1,0),(0,1),(1,1) -> t=(g8>>1)*8+r8, e=(g8&1)*8
    const uint32_t aOff = (uint32_t)(((g8 >> 1) * 8 + r8) * KSTR + wid * 16 + (g8 & 1) * 8) * 2;
    // trans-B (K^T): quads (N,K)=(0,0),(0,1),(1,0),(1,1) -> t=(g8&1)*8+r8, d=(g8>>1)*8
    const uint32_t bOff = (uint32_t)(((g8 & 1) * 8 + r8) * KSTR + (g8 >> 1) * 8) * 2;

    const uint32_t sKb = smem_u32(sK);
    const uint32_t sVb = smem_u32(sV);

    float acc[8][4];
#pragma unroll
    for (int j = 0; j < 8; j++)
#pragma unroll
        for (int k = 0; k < 4; k++) acc[j][k] = 0.f;
    float ks = 0.f;

    for (int c0 = 0; c0 < KVROWS; c0 += 64) {
#pragma unroll
        for (int i = 0; i < 4; i++) {
            int idx = tid + i * 128;         // 0..511
            int row = idx >> 3;
            int c8 = idx & 7;
            *(uint4*)(sK + row * KSTR + c8 * 8) =
                *(const uint4*)(g_Kh + base + (size_t)(c0 + row) * Cc + c8 * 8);
            *(uint4*)(sV + row * KSTR + c8 * 8) =
                *(const uint4*)(g_Vh + base + (size_t)(c0 + row) * Cc + c8 * 8);
        }
        __syncthreads();

        // Ksum partial (threads 0..63, column d = tid)
        if (tid < 64) {
#pragma unroll
            for (int r = 0; r < 64; r++) ks += __half2float(sK[r * KSTR + tid]);
        }

#pragma unroll
        for (int kt = 0; kt < 4; kt++) {     // 4 x k16 over the 64 t-rows
            uint32_t af[4];
            ldsm_x4_t(af, sVb + aOff + (uint32_t)(kt * 16 * KSTR) * 2);
            uint32_t bf[4][4];
#pragma unroll
            for (int p = 0; p < 4; p++)      // d blocks of 16
                ldsm_x4_t(bf[p], sKb + bOff + (uint32_t)(kt * 16 * KSTR) * 2 + p * 32);
#pragma unroll
            for (int p = 0; p < 4; p++) {
                mma_f16(acc[p * 2 + 0], af, bf[p][0], bf[p][1]);
                mma_f16(acc[p * 2 + 1], af, bf[p][2], bf[p][3]);
            }
        }
        __syncthreads();
    }

    // store partials: [e][d] order, fp32
    float* kvp = g_KVp + ((size_t)split * BH + bh) * (Dd * Dd);
    const int r_lo = lane >> 2;
    const int c_off = (lane & 3) * 2;
#pragma unroll
    for (int nj = 0; nj < 8; nj++) {
        int d = nj * 8 + c_off;
#pragma unroll
        for (int half_ = 0; half_ < 2; half_++) {
            int e = wid * 16 + r_lo + half_ * 8;
            *(float2*)(kvp + e * Dd + d) =
                make_float2(acc[nj][half_ * 2 + 0], acc[nj][half_ * 2 + 1]);
        }
    }
    if (tid < 64)
        g_Ksp[((size_t)split * BH + bh) * Dd + tid] = ks;
}

// Reduce partials -> Ksum (fp32) and KVt (fp16, already [e][d]). grid = BH.
__global__ __launch_bounds__(256) void kv_reduce()
{
    const int bh = blockIdx.x;
    const int tid = threadIdx.x;

#pragma unroll
    for (int j = 0; j < 16; j++) {
        int idx = j * 256 + tid;             // e*64+d
        float s = 0.f;
#pragma unroll
        for (int p = 0; p < KV_SPLIT; p++)
            s += g_KVp[((size_t)p * BH + bh) * (Dd * Dd) + idx];
        g_KVt[(size_t)bh * (Dd * Dd) + idx] = __float2half(s);
    }
    if (tid < 64) {
        float s = 0.f;
#pragma unroll
        for (int p = 0; p < KV_SPLIT; p++)
            s += g_Ksp[((size_t)p * BH + bh) * Dd + tid];
        g_Ksum[bh * Dd + tid] = s;
    }
}

// ---------------- tensor-core Y kernel ----------------
#define YSTR 72
__global__ __launch_bounds__(128) void y_mma()
{
    const int bh = blockIdx.y;
    const int b = bh >> 3, h = bh & 7;
    const int t0 = blockIdx.x * 64;
    const int tid = threadIdx.x;
    const int wid = tid >> 5;
    const int lane = tid & 31;

    __shared__ __align__(16) __half sQ[64 * YSTR];
    __shared__ __align__(16) __half sB[64 * YSTR];
    __shared__ float sKs[64];
    __shared__ float sInv[64];

#pragma unroll
    for (int i = 0; i < 4; i++) {
        int idx = tid + i * 128;
        int row = idx >> 3;
        int c8 = idx & 7;
        *(uint4*)(sQ + row * YSTR + c8 * 8) =
            *(const uint4*)(g_Qh + ((size_t)b * Tt + t0 + row) * Cc + h * Dd + c8 * 8);
        *(uint4*)(sB + row * YSTR + c8 * 8) =
            *(const uint4*)(g_KVt + (size_t)bh * (Dd * Dd) + (size_t)row * Dd + c8 * 8);
    }
    if (tid < 64) sKs[tid] = g_Ksum[bh * Dd + tid];
    __syncthreads();

    if (tid < 64) {
        float s = 0.f;
#pragma unroll
        for (int d = 0; d < 64; d++)
            s = fmaf(__half2float(sQ[tid * YSTR + d]), sKs[d], s);
        sInv[tid] = 1.f / (s + 1e-6f);
    }

    const int g8 = lane >> 3;
    const int r8 = lane & 7;
    const int a_row_l = r8 + (g8 & 1) * 8;
    const int a_kb    = (g8 >> 1) * 16;
    const int b_row_l = r8 + (g8 >> 1) * 8;
    const int b_kb    = (g8 & 1) * 16;

    const uint32_t qB = smem_u32(sQ) + (uint32_t)((wid * 16 + a_row_l) * YSTR) * 2 + a_kb;
    const uint32_t bB = smem_u32(sB) + (uint32_t)(b_row_l * YSTR) * 2 + b_kb;

    float acc[8][4];
#pragma unroll
    for (int j = 0; j < 8; j++)
#pragma unroll
        for (int k = 0; k < 4; k++) acc[j][k] = 0.f;

    __syncthreads();

#pragma unroll
    for (int ks = 0; ks < 4; ks++) {
        uint32_t af[4];
        ldsm_x4(af, qB + ks * 32);
        uint32_t bf[4][4];
#pragma unroll
        for (int p = 0; p < 4; p++)
            ldsm_x4(bf[p], bB + (uint32_t)(p * 16 * YSTR) * 2 + ks * 32);
#pragma unroll
        for (int p = 0; p < 4; p++) {
            mma_f16(acc[p * 2 + 0], af, bf[p][0], bf[p][1]);
            mma_f16(acc[p * 2 + 1], af, bf[p][2], bf[p][3]);
        }
    }

    const int r_lo = lane >> 2;
    const int c_off = (lane & 3) * 2;
#pragma unroll
    for (int nj = 0; nj < 8; nj++) {
        int col = nj * 8 + c_off;
#pragma unroll
        for (int half_ = 0; half_ < 2; half_++) {
            int tok = wid * 16 + r_lo + half_ * 8;
            float inv = sInv[tok];
            __half2 hv = __floats2half2_rn(acc[nj][half_ * 2 + 0] * inv,
                                           acc[nj][half_ * 2 + 1] * inv);
            *(__half2*)(g_Yh + ((size_t)b * Tt + t0 + tok) * Cc + h * Dd + col) = hv;
        }
    }
}

// ---------------- launch ----------------
extern "C" void kernel_launch(void* const* d_in, const int* in_sizes, int n_in,
                              void* d_out, int out_size)
{
    const float* x  = (const float*)d_in[0];
    const float* Wq = (const float*)d_in[1];
    const float* bq = (const float*)d_in[2];
    const float* Wk = (const float*)d_in[3];
    const float* bk = (const float*)d_in[4];
    const float* Wv = (const float*)d_in[5];
    const float* bv = (const float*)d_in[6];
    const float* Wo = (const float*)d_in[7];
    const float* bo = (const float*)d_in[8];
    float* out = (float*)d_out;

    static __half *pXh = nullptr, *pWh, *pQh, *pKh, *pVh, *pYh;
    static bool inited = false;
    if (!inited) {
        cudaGetSymbolAddress((void**)&pXh, g_Xh);
        cudaGetSymbolAddress((void**)&pWh, g_Wh);
        cudaGetSymbolAddress((void**)&pQh, g_Qh);
        cudaGetSymbolAddress((void**)&pKh, g_Kh);
        cudaGetSymbolAddress((void**)&pVh, g_Vh);
        cudaGetSymbolAddress((void**)&pYh, g_Yh);
        cudaFuncSetAttribute(gemm_qkv, cudaFuncAttributeMaxDynamicSharedMemorySize, GEMM_SMEM);
        cudaFuncSetAttribute(gemm_out, cudaFuncAttributeMaxDynamicSharedMemorySize, GEMM_SMEM);
        inited = true;
    }

    // f32 -> f16 conversions
    {
        int n8 = NN * Cc / 8;
        cvt_f16<<<n8 / 256, 256>>>((const float4*)x, (uint4*)pXh, n8);
        int tot = 4 * Cc * Cc / 8;
        cvt_w<<<(tot + 255) / 256, 256>>>((const float4*)Wq, (const float4*)Wk,
                                          (const float4*)Wv, (const float4*)Wo, (uint4*)pWh);
    }

    // Fused Q/K/V projections
    gemm_qkv<<<dim3(NN / BM, 12), 256, GEMM_SMEM>>>(pXh, pWh, bq, bk, bv, pQh, pKh, pVh);

    // Tensor-core KV accumulation -> reduce -> tensor-core Y
    kv_mma<<<dim3(BH, KV_SPLIT), 128>>>();
    kv_reduce<<<BH, 256>>>();
    y_mma<<<dim3(Tt / 64, BH), 128>>>();

    // Output projection
    gemm_out<<<dim3(NN / BM, Cc / BN), 256, GEMM_SMEM>>>(pYh, pWh + 3 * (size_t)Cc * Cc, bo, out);
}

// round 13
// speedup vs baseline: 2.0019x; 1.0480x over previous
#include <cuda_runtime.h>
#include <cuda_fp16.h>
#include <math.h>
#include <stdint.h>

// ---------------- Problem constants ----------------
#define Bb 8
#define Tt 8192
#define Cc 512
#define Hh 8
#define Dd 64
#define NN (Bb*Tt)         // 65536 tokens
#define BH (Bb*Hh)         // 64
#define KV_SPLIT 16
#define KVROWS (Tt / KV_SPLIT)   // 512

// ---------------- Scratch (device globals) ----------------
__device__ __half g_Xh[(size_t)NN*Cc];
__device__ __half g_Wh[(size_t)4*Cc*Cc];
__device__ __half g_Qh[(size_t)NN*Cc];
__device__ __half g_Kh[(size_t)NN*Cc];
__device__ __half g_Vh[(size_t)NN*Cc];
__device__ __half g_Yh[(size_t)NN*Cc];
__device__ float  g_KVp[(size_t)KV_SPLIT*BH*Dd*Dd];   // partial KVt sums ([e][d] order)
__device__ float  g_Ksp[(size_t)KV_SPLIT*BH*Dd];      // partial Ksum
__device__ __half g_KVt[(size_t)BH*Dd*Dd];            // KV^T (e-major) fp16
__device__ float  g_Ksum[(size_t)BH*Dd];

// ---------------- helpers ----------------
__device__ __forceinline__ uint32_t smem_u32(const void* p) {
    uint32_t a;
    asm("{ .reg .u64 t; cvta.to.shared.u64 t, %1; cvt.u32.u64 %0, t; }" : "=r"(a) : "l"(p));
    return a;
}
#define CP_ASYNC16(dst, src) \
    asm volatile("cp.async.cg.shared.global [%0], [%1], 16;" :: "r"(dst), "l"(src) : "memory")
#define CP_COMMIT() asm volatile("cp.async.commit_group;" ::: "memory")
#define CP_WAIT(n)  asm volatile("cp.async.wait_group %0;" :: "n"(n) : "memory")

__device__ __forceinline__ void ldsm_x4(uint32_t* r, uint32_t addr) {
    asm volatile("ldmatrix.sync.aligned.m8n8.x4.shared.b16 {%0,%1,%2,%3}, [%4];"
                 : "=r"(r[0]), "=r"(r[1]), "=r"(r[2]), "=r"(r[3]) : "r"(addr));
}
__device__ __forceinline__ void ldsm_x4_t(uint32_t* r, uint32_t addr) {
    asm volatile("ldmatrix.sync.aligned.m8n8.x4.trans.shared.b16 {%0,%1,%2,%3}, [%4];"
                 : "=r"(r[0]), "=r"(r[1]), "=r"(r[2]), "=r"(r[3]) : "r"(addr));
}
__device__ __forceinline__ void mma_f16(float* c, const uint32_t* a, uint32_t b0, uint32_t b1) {
    asm volatile("mma.sync.aligned.m16n8k16.row.col.f32.f16.f16.f32 "
                 "{%0,%1,%2,%3},{%4,%5,%6,%7},{%8,%9},{%0,%1,%2,%3};"
                 : "+f"(c[0]), "+f"(c[1]), "+f"(c[2]), "+f"(c[3])
                 : "r"(a[0]), "r"(a[1]), "r"(a[2]), "r"(a[3]), "r"(b0), "r"(b1));
}

// ---------------- GEMM config (fp16, 128x128 CTA, 8 warps of 64x32) ----------------
#define BM 128
#define BN 128
#define BKH 64
#define NKH (Cc / BKH)
#define ASTRH 72
#define TILEH (BM * ASTRH)
#define STAGEH (2 * TILEH)
#define NSTG 3
#define GEMM_SMEM (NSTG * STAGEH * 2)   // 110592 bytes

__device__ __forceinline__ void gemm_core(
    const __half* __restrict__ A, const __half* __restrict__ B,
    int m0, int n0, __half* smh, float acc[4][4][4])
{
    const int tid = threadIdx.x;
    const int wid = tid >> 5;
    const int lane = tid & 31;
    const int m_warp = (wid >> 2) * 64;
    const int n_warp = (wid & 3) * 32;

    const int g8 = lane >> 3;
    const int r8 = lane & 7;
    const int a_row_l = r8 + (g8 & 1) * 8;
    const int a_kb    = (g8 >> 1) * 16;
    const int b_row_l = r8 + (g8 >> 1) * 8;
    const int b_kb    = (g8 & 1) * 16;

    const uint32_t smb = smem_u32(smh);

#pragma unroll
    for (int i = 0; i < 4; i++)
#pragma unroll
        for (int j = 0; j < 4; j++)
#pragma unroll
            for (int k = 0; k < 4; k++) acc[i][j][k] = 0.f;

    auto load_stage = [&](int kc, int s) {
        const __half* gA = A + (size_t)m0 * Cc + kc * BKH;
        const __half* gB = B + (size_t)n0 * Cc + kc * BKH;
        uint32_t dA = smb + (uint32_t)(s * STAGEH) * 2;
        uint32_t dB = dA + (uint32_t)TILEH * 2;
#pragma unroll
        for (int i = 0; i < 4; i++) {
            int idx = tid + i * 256;
            int row = idx >> 3;
            int c8 = idx & 7;
            CP_ASYNC16(dA + (uint32_t)(row * ASTRH + c8 * 8) * 2, gA + (size_t)row * Cc + c8 * 8);
        }
#pragma unroll
        for (int i = 0; i < 4; i++) {
            int idx = tid + i * 256;
            int row = idx >> 3;
            int c8 = idx & 7;
            CP_ASYNC16(dB + (uint32_t)(row * ASTRH + c8 * 8) * 2, gB + (size_t)row * Cc + c8 * 8);
        }
        CP_COMMIT();
    };

    load_stage(0, 0);
    load_stage(1, 1);

    for (int kt = 0; kt < NKH; kt++) {
        if (kt < NKH - 1) CP_WAIT(1); else CP_WAIT(0);
        __syncthreads();
        if (kt + 2 < NKH) load_stage(kt + 2, (kt + 2) % 3);

        const int s = kt % 3;
        const uint32_t aB = smb + (uint32_t)(s * STAGEH) * 2
                          + (uint32_t)((m_warp + a_row_l) * ASTRH) * 2 + a_kb;
        const uint32_t bB = smb + (uint32_t)(s * STAGEH + TILEH) * 2
                          + (uint32_t)((n_warp + b_row_l) * ASTRH) * 2 + b_kb;

#pragma unroll
        for (int ks = 0; ks < 4; ks++) {
            uint32_t af[4][4];
#pragma unroll
            for (int mi = 0; mi < 4; mi++)
                ldsm_x4(af[mi], aB + (uint32_t)(mi * 16 * ASTRH) * 2 + ks * 32);
            uint32_t bf[2][4];
#pragma unroll
            for (int p = 0; p < 2; p++)
                ldsm_x4(bf[p], bB + (uint32_t)(p * 16 * ASTRH) * 2 + ks * 32);
#pragma unroll
            for (int mi = 0; mi < 4; mi++) {
#pragma unroll
                for (int p = 0; p < 2; p++) {
                    mma_f16(acc[mi][p * 2 + 0], af[mi], bf[p][0], bf[p][1]);
                    mma_f16(acc[mi][p * 2 + 1], af[mi], bf[p][2], bf[p][3]);
                }
            }
        }
    }
}

__device__ __forceinline__ void epilogue_h(
    float acc[4][4][4], const float* bias, __half* outp, int m0, int n0, int act)
{
    const int tid = threadIdx.x;
    const int wid = tid >> 5;
    const int lane = tid & 31;
    const int m_warp = (wid >> 2) * 64;
    const int n_warp = (wid & 3) * 32;
    const int r_lo = lane >> 2;
    const int c_off = (lane & 3) * 2;
#pragma unroll
    for (int mi = 0; mi < 4; mi++) {
#pragma unroll
        for (int nj = 0; nj < 4; nj++) {
            int col = n0 + n_warp + nj * 8 + c_off;
            float b0 = bias[col], b1 = bias[col + 1];
#pragma unroll
            for (int half_ = 0; half_ < 2; half_++) {
                int row = m0 + m_warp + mi * 16 + r_lo + half_ * 8;
                float v0 = acc[mi][nj][half_ * 2 + 0] + b0;
                float v1 = acc[mi][nj][half_ * 2 + 1] + b1;
                if (act) {
                    v0 = (v0 > 0.f) ? v0 + 1.f : expf(v0);
                    v1 = (v1 > 0.f) ? v1 + 1.f : expf(v1);
                }
                __half2 hv = __floats2half2_rn(v0, v1);
                *(__half2*)(outp + (size_t)row * Cc + col) = hv;
            }
        }
    }
}

// Fused QKV projection: grid (NN/BM, 12). Segment = by>>2: 0=Q,1=K,2=V.
__global__ __launch_bounds__(256, 2)
void gemm_qkv(const __half* __restrict__ X, const __half* __restrict__ W,
              const float* __restrict__ bq, const float* __restrict__ bk,
              const float* __restrict__ bv,
              __half* __restrict__ Q, __half* __restrict__ K, __half* __restrict__ V)
{
    extern __shared__ __half smh[];
    const int seg = blockIdx.y >> 2;
    const int n0 = (blockIdx.y & 3) * BN;
    const int m0 = blockIdx.x * BM;

    const __half* B = W + (size_t)seg * Cc * Cc;
    const float* bias = (seg == 0) ? bq : (seg == 1) ? bk : bv;
    __half* outp = (seg == 0) ? Q : (seg == 1) ? K : V;
    const int act = (seg < 2);

    float acc[4][4][4];
    gemm_core(X, B, m0, n0, smh, acc);
    epilogue_h(acc, bias, outp, m0, n0, act);
}

// Output projection: f32 store, no activation.
__global__ __launch_bounds__(256, 2)
void gemm_out(const __half* __restrict__ Y, const __half* __restrict__ W,
              const float* __restrict__ bias, float* __restrict__ outp)
{
    extern __shared__ __half smh[];
    const int m0 = blockIdx.x * BM;
    const int n0 = blockIdx.y * BN;

    float acc[4][4][4];
    gemm_core(Y, W, m0, n0, smh, acc);

    const int tid = threadIdx.x;
    const int wid = tid >> 5;
    const int lane = tid & 31;
    const int m_warp = (wid >> 2) * 64;
    const int n_warp = (wid & 3) * 32;
    const int r_lo = lane >> 2;
    const int c_off = (lane & 3) * 2;
#pragma unroll
    for (int mi = 0; mi < 4; mi++) {
#pragma unroll
        for (int nj = 0; nj < 4; nj++) {
            int col = n0 + n_warp + nj * 8 + c_off;
            float b0 = bias[col], b1 = bias[col + 1];
#pragma unroll
            for (int half_ = 0; half_ < 2; half_++) {
                int row = m0 + m_warp + mi * 16 + r_lo + half_ * 8;
                float v0 = acc[mi][nj][half_ * 2 + 0] + b0;
                float v1 = acc[mi][nj][half_ * 2 + 1] + b1;
                *(float2*)(outp + (size_t)row * Cc + col) = make_float2(v0, v1);
            }
        }
    }
}

// ---------------- f32 -> f16 conversions ----------------
__global__ __launch_bounds__(256) void cvt_f16(const float4* __restrict__ src,
                                               uint4* __restrict__ dst, int n8)
{
    int i = blockIdx.x * blockDim.x + threadIdx.x;
    if (i < n8) {
        float4 a = src[2 * i], b = src[2 * i + 1];
        __half2 h0 = __floats2half2_rn(a.x, a.y);
        __half2 h1 = __floats2half2_rn(a.z, a.w);
        __half2 h2 = __floats2half2_rn(b.x, b.y);
        __half2 h3 = __floats2half2_rn(b.z, b.w);
        uint4 o;
        o.x = *(uint32_t*)&h0; o.y = *(uint32_t*)&h1;
        o.z = *(uint32_t*)&h2; o.w = *(uint32_t*)&h3;
        dst[i] = o;
    }
}

__global__ __launch_bounds__(256) void cvt_w(
    const float4* __restrict__ w0, const float4* __restrict__ w1,
    const float4* __restrict__ w2, const float4* __restrict__ w3,
    uint4* __restrict__ dst)
{
    const int w8 = Cc * Cc / 8;
    int i = blockIdx.x * blockDim.x + threadIdx.x;
    if (i >= 4 * w8) return;
    int seg = i / w8, j = i - seg * w8;
    const float4* src = (seg == 0) ? w0 : (seg == 1) ? w1 : (seg == 2) ? w2 : w3;
    float4 a = src[2 * j], b = src[2 * j + 1];
    __half2 h0 = __floats2half2_rn(a.x, a.y);
    __half2 h1 = __floats2half2_rn(a.z, a.w);
    __half2 h2 = __floats2half2_rn(b.x, b.y);
    __half2 h3 = __floats2half2_rn(b.z, b.w);
    uint4 o;
    o.x = *(uint32_t*)&h0; o.y = *(uint32_t*)&h1;
    o.z = *(uint32_t*)&h2; o.w = *(uint32_t*)&h3;
    dst[i] = o;
}

// ---------------- tensor-core KV accumulation (pipelined, 256 thr) ----------------
// KVt_partial[e][d] = sum_t V[t][e] * K[t][d] over this split's 512 rows.
// 8 warps: e slab = (wid&3)*16, d slab = (wid>>2)*32.
#define KSTR 72
#define KTILEH (64 * KSTR)            // one operand tile (halves)
#define KSTAGEH (2 * KTILEH)          // K + V
__global__ __launch_bounds__(256) void kv_mma()
{
    const int bh = blockIdx.x;
    const int b = bh >> 3, h = bh & 7;
    const int split = blockIdx.y;
    const int tid = threadIdx.x;
    const int wid = tid >> 5;
    const int lane = tid & 31;
    const size_t base = ((size_t)b * Tt + (size_t)split * KVROWS) * Cc + h * Dd;

    __shared__ __align__(16) __half sm[2 * KSTAGEH];   // [stage][K tile | V tile]
    __shared__ float sKs4[4][64];
    const uint32_t smb = smem_u32(sm);

    const int e_w = (wid & 3) * 16;
    const int d_w = (wid >> 2) * 32;

    const int g8 = lane >> 3;
    const int r8 = lane & 7;
    // trans-A (V^T): t=(g8>>1)*8+r8, e offset=(g8&1)*8
    const uint32_t aOff = (uint32_t)(((g8 >> 1) * 8 + r8) * KSTR + e_w + (g8 & 1) * 8) * 2;
    // trans-B (K^T): t=(g8&1)*8+r8, d offset=(g8>>1)*8
    const uint32_t bOff = (uint32_t)(((g8 & 1) * 8 + r8) * KSTR + d_w + (g8 >> 1) * 8) * 2;

    // Ksum assignment: thread sums rows [(tid>>6)*16, +16) for d = tid&63
    const int ks_d = tid & 63;
    const int ks_r0 = (tid >> 6) * 16;

    auto load_chunk = [&](int c0, int s) {
        uint32_t dK = smb + (uint32_t)(s * KSTAGEH) * 2;
        uint32_t dV = dK + (uint32_t)KTILEH * 2;
#pragma unroll
        for (int i = 0; i < 2; i++) {
            int idx = tid + i * 256;         // 0..511
            int row = idx >> 3;
            int c8 = idx & 7;
            CP_ASYNC16(dK + (uint32_t)(row * KSTR + c8 * 8) * 2,
                       g_Kh + base + (size_t)(c0 + row) * Cc + c8 * 8);
            CP_ASYNC16(dV + (uint32_t)(row * KSTR + c8 * 8) * 2,
                       g_Vh + base + (size_t)(c0 + row) * Cc + c8 * 8);
        }
        CP_COMMIT();
    };

    float acc[4][4];
#pragma unroll
    for (int j = 0; j < 4; j++)
#pragma unroll
        for (int k = 0; k < 4; k++) acc[j][k] = 0.f;
    float ks = 0.f;

    load_chunk(0, 0);

    const int NCH = KVROWS / 64;   // 8
    for (int c = 0; c < NCH; c++) {
        if (c + 1 < NCH) {
            load_chunk((c + 1) * 64, (c + 1) & 1);
            CP_WAIT(1);
        } else {
            CP_WAIT(0);
        }
        __syncthreads();

        const int s = c & 1;
        const uint32_t sKb = smb + (uint32_t)(s * KSTAGEH) * 2;
        const uint32_t sVb = sKb + (uint32_t)KTILEH * 2;
        const __half* sKh = sm + s * KSTAGEH;

        // Ksum partial (all 256 threads, 16 rows each)
#pragma unroll
        for (int r = 0; r < 16; r++)
            ks += __half2float(sKh[(ks_r0 + r) * KSTR + ks_d]);

#pragma unroll
        for (int kt = 0; kt < 4; kt++) {
            uint32_t af[4];
            ldsm_x4_t(af, sVb + aOff + (uint32_t)(kt * 16 * KSTR) * 2);
            uint32_t bf[2][4];
#pragma unroll
            for (int p = 0; p < 2; p++)
                ldsm_x4_t(bf[p], sKb + bOff + (uint32_t)(kt * 16 * KSTR) * 2 + p * 32);
#pragma unroll
            for (int p = 0; p < 2; p++) {
                mma_f16(acc[p * 2 + 0], af, bf[p][0], bf[p][1]);
                mma_f16(acc[p * 2 + 1], af, bf[p][2], bf[p][3]);
            }
        }
        __syncthreads();
    }

    // store partials: [e][d] order, fp32
    float* kvp = g_KVp + ((size_t)split * BH + bh) * (Dd * Dd);
    const int r_lo = lane >> 2;
    const int c_off = (lane & 3) * 2;
#pragma unroll
    for (int nj = 0; nj < 4; nj++) {
        int d = d_w + nj * 8 + c_off;
#pragma unroll
        for (int half_ = 0; half_ < 2; half_++) {
            int e = e_w + r_lo + half_ * 8;
            *(float2*)(kvp + e * Dd + d) =
                make_float2(acc[nj][half_ * 2 + 0], acc[nj][half_ * 2 + 1]);
        }
    }
    // Ksum 4-way reduce
    sKs4[tid >> 6][ks_d] = ks;   // NOTE: only valid because each (group,d) pair unique
    __syncthreads();
    if (tid < 64)
        g_Ksp[((size_t)split * BH + bh) * Dd + tid] =
            sKs4[0][tid] + sKs4[1][tid] + sKs4[2][tid] + sKs4[3][tid];
}

// Reduce partials -> Ksum (fp32) and KVt (fp16, already [e][d]). grid = BH.
__global__ __launch_bounds__(256) void kv_reduce()
{
    const int bh = blockIdx.x;
    const int tid = threadIdx.x;

#pragma unroll
    for (int j = 0; j < 16; j++) {
        int idx = j * 256 + tid;             // e*64+d
        float s = 0.f;
#pragma unroll
        for (int p = 0; p < KV_SPLIT; p++)
            s += g_KVp[((size_t)p * BH + bh) * (Dd * Dd) + idx];
        g_KVt[(size_t)bh * (Dd * Dd) + idx] = __float2half(s);
    }
    if (tid < 64) {
        float s = 0.f;
#pragma unroll
        for (int p = 0; p < KV_SPLIT; p++)
            s += g_Ksp[((size_t)p * BH + bh) * Dd + tid];
        g_Ksum[bh * Dd + tid] = s;
    }
}

// ---------------- tensor-core Y kernel ----------------
#define YSTR 72
__global__ __launch_bounds__(128) void y_mma()
{
    const int bh = blockIdx.y;
    const int b = bh >> 3, h = bh & 7;
    const int t0 = blockIdx.x * 64;
    const int tid = threadIdx.x;
    const int wid = tid >> 5;
    const int lane = tid & 31;

    __shared__ __align__(16) __half sQ[64 * YSTR];
    __shared__ __align__(16) __half sB[64 * YSTR];
    __shared__ float sKs[64];
    __shared__ float sInv[64];

#pragma unroll
    for (int i = 0; i < 4; i++) {
        int idx = tid + i * 128;
        int row = idx >> 3;
        int c8 = idx & 7;
        *(uint4*)(sQ + row * YSTR + c8 * 8) =
            *(const uint4*)(g_Qh + ((size_t)b * Tt + t0 + row) * Cc + h * Dd + c8 * 8);
        *(uint4*)(sB + row * YSTR + c8 * 8) =
            *(const uint4*)(g_KVt + (size_t)bh * (Dd * Dd) + (size_t)row * Dd + c8 * 8);
    }
    if (tid < 64) sKs[tid] = g_Ksum[bh * Dd + tid];
    __syncthreads();

    if (tid < 64) {
        float s = 0.f;
#pragma unroll
        for (int d = 0; d < 64; d++)
            s = fmaf(__half2float(sQ[tid * YSTR + d]), sKs[d], s);
        sInv[tid] = 1.f / (s + 1e-6f);
    }

    const int g8 = lane >> 3;
    const int r8 = lane & 7;
    const int a_row_l = r8 + (g8 & 1) * 8;
    const int a_kb    = (g8 >> 1) * 16;
    const int b_row_l = r8 + (g8 >> 1) * 8;
    const int b_kb    = (g8 & 1) * 16;

    const uint32_t qB = smem_u32(sQ) + (uint32_t)((wid * 16 + a_row_l) * YSTR) * 2 + a_kb;
    const uint32_t bB = smem_u32(sB) + (uint32_t)(b_row_l * YSTR) * 2 + b_kb;

    float acc[8][4];
#pragma unroll
    for (int j = 0; j < 8; j++)
#pragma unroll
        for (int k = 0; k < 4; k++) acc[j][k] = 0.f;

    __syncthreads();

#pragma unroll
    for (int ks = 0; ks < 4; ks++) {
        uint32_t af[4];
        ldsm_x4(af, qB + ks * 32);
        uint32_t bf[4][4];
#pragma unroll
        for (int p = 0; p < 4; p++)
            ldsm_x4(bf[p], bB + (uint32_t)(p * 16 * YSTR) * 2 + ks * 32);
#pragma unroll
        for (int p = 0; p < 4; p++) {
            mma_f16(acc[p * 2 + 0], af, bf[p][0], bf[p][1]);
            mma_f16(acc[p * 2 + 1], af, bf[p][2], bf[p][3]);
        }
    }

    const int r_lo = lane >> 2;
    const int c_off = (lane & 3) * 2;
#pragma unroll
    for (int nj = 0; nj < 8; nj++) {
        int col = nj * 8 + c_off;
#pragma unroll
        for (int half_ = 0; half_ < 2; half_++) {
            int tok = wid * 16 + r_lo + half_ * 8;
            float inv = sInv[tok];
            __half2 hv = __floats2half2_rn(acc[nj][half_ * 2 + 0] * inv,
                                           acc[nj][half_ * 2 + 1] * inv);
            *(__half2*)(g_Yh + ((size_t)b * Tt + t0 + tok) * Cc + h * Dd + col) = hv;
        }
    }
}

// ---------------- launch ----------------
extern "C" void kernel_launch(void* const* d_in, const int* in_sizes, int n_in,
                              void* d_out, int out_size)
{
    const float* x  = (const float*)d_in[0];
    const float* Wq = (const float*)d_in[1];
    const float* bq = (const float*)d_in[2];
    const float* Wk = (const float*)d_in[3];
    const float* bk = (const float*)d_in[4];
    const float* Wv = (const float*)d_in[5];
    const float* bv = (const float*)d_in[6];
    const float* Wo = (const float*)d_in[7];
    const float* bo = (const float*)d_in[8];
    float* out = (float*)d_out;

    static __half *pXh = nullptr, *pWh, *pQh, *pKh, *pVh, *pYh;
    static bool inited = false;
    if (!inited) {
        cudaGetSymbolAddress((void**)&pXh, g_Xh);
        cudaGetSymbolAddress((void**)&pWh, g_Wh);
        cudaGetSymbolAddress((void**)&pQh, g_Qh);
        cudaGetSymbolAddress((void**)&pKh, g_Kh);
        cudaGetSymbolAddress((void**)&pVh, g_Vh);
        cudaGetSymbolAddress((void**)&pYh, g_Yh);
        cudaFuncSetAttribute(gemm_qkv, cudaFuncAttributeMaxDynamicSharedMemorySize, GEMM_SMEM);
        cudaFuncSetAttribute(gemm_out, cudaFuncAttributeMaxDynamicSharedMemorySize, GEMM_SMEM);
        inited = true;
    }

    // f32 -> f16 conversions
    {
        int n8 = NN * Cc / 8;
        cvt_f16<<<n8 / 256, 256>>>((const float4*)x, (uint4*)pXh, n8);
        int tot = 4 * Cc * Cc / 8;
        cvt_w<<<(tot + 255) / 256, 256>>>((const float4*)Wq, (const float4*)Wk,
                                          (const float4*)Wv, (const float4*)Wo, (uint4*)pWh);
    }

    // Fused Q/K/V projections
    gemm_qkv<<<dim3(NN / BM, 12), 256, GEMM_SMEM>>>(pXh, pWh, bq, bk, bv, pQh, pKh, pVh);

    // Tensor-core KV accumulation (pipelined) -> reduce -> tensor-core Y
    kv_mma<<<dim3(BH, KV_SPLIT), 256>>>();
    kv_reduce<<<BH, 256>>>();
    y_mma<<<dim3(Tt / 64, BH), 128>>>();

    // Output projection
    gemm_out<<<dim3(NN / BM, Cc / BN), 256, GEMM_SMEM>>>(pYh, pWh + 3 * (size_t)Cc * Cc, bo, out);
}

// round 14
// speedup vs baseline: 2.0404x; 1.0192x over previous
#include <cuda_runtime.h>
#include <cuda_fp16.h>
#include <math.h>
#include <stdint.h>

// ---------------- Problem constants ----------------
#define Bb 8
#define Tt 8192
#define Cc 512
#define Hh 8
#define Dd 64
#define NN (Bb*Tt)         // 65536 tokens
#define BH (Bb*Hh)         // 64
#define KV_SPLIT 8
#define KVROWS (Tt / KV_SPLIT)   // 1024

// ---------------- Scratch (device globals) ----------------
__device__ __half g_Xh[(size_t)NN*Cc];
__device__ __half g_Wh[(size_t)4*Cc*Cc];
__device__ __half g_Qh[(size_t)NN*Cc];
__device__ __half g_Kh[(size_t)NN*Cc];
__device__ __half g_Vh[(size_t)NN*Cc];
__device__ __half g_Yh[(size_t)NN*Cc];
__device__ float  g_KVp[(size_t)KV_SPLIT*BH*Dd*Dd];   // partial KVt sums ([e][d] order)
__device__ float  g_Ksp[(size_t)KV_SPLIT*BH*Dd];      // partial Ksum
__device__ __half g_KVt[(size_t)BH*Dd*Dd];            // KV^T (e-major) fp16
__device__ float  g_Ksum[(size_t)BH*Dd];

// ---------------- helpers ----------------
__device__ __forceinline__ uint32_t smem_u32(const void* p) {
    uint32_t a;
    asm("{ .reg .u64 t; cvta.to.shared.u64 t, %1; cvt.u32.u64 %0, t; }" : "=r"(a) : "l"(p));
    return a;
}
#define CP_ASYNC16(dst, src) \
    asm volatile("cp.async.cg.shared.global [%0], [%1], 16;" :: "r"(dst), "l"(src) : "memory")
#define CP_COMMIT() asm volatile("cp.async.commit_group;" ::: "memory")
#define CP_WAIT(n)  asm volatile("cp.async.wait_group %0;" :: "n"(n) : "memory")

__device__ __forceinline__ void ldsm_x4(uint32_t* r, uint32_t addr) {
    asm volatile("ldmatrix.sync.aligned.m8n8.x4.shared.b16 {%0,%1,%2,%3}, [%4];"
                 : "=r"(r[0]), "=r"(r[1]), "=r"(r[2]), "=r"(r[3]) : "r"(addr));
}
__device__ __forceinline__ void ldsm_x4_t(uint32_t* r, uint32_t addr) {
    asm volatile("ldmatrix.sync.aligned.m8n8.x4.trans.shared.b16 {%0,%1,%2,%3}, [%4];"
                 : "=r"(r[0]), "=r"(r[1]), "=r"(r[2]), "=r"(r[3]) : "r"(addr));
}
__device__ __forceinline__ void mma_f16(float* c, const uint32_t* a, uint32_t b0, uint32_t b1) {
    asm volatile("mma.sync.aligned.m16n8k16.row.col.f32.f16.f16.f32 "
                 "{%0,%1,%2,%3},{%4,%5,%6,%7},{%8,%9},{%0,%1,%2,%3};"
                 : "+f"(c[0]), "+f"(c[1]), "+f"(c[2]), "+f"(c[3])
                 : "r"(a[0]), "r"(a[1]), "r"(a[2]), "r"(a[3]), "r"(b0), "r"(b1));
}

// ---------------- GEMM config (fp16, 128x128 CTA, 8 warps of 64x32) ----------------
#define BM 128
#define BN 128
#define BKH 64
#define NKH (Cc / BKH)
#define ASTRH 72
#define TILEH (BM * ASTRH)
#define STAGEH (2 * TILEH)
#define NSTG 3
#define GEMM_SMEM (NSTG * STAGEH * 2)   // 110592 bytes

__device__ __forceinline__ void gemm_core(
    const __half* __restrict__ A, const __half* __restrict__ B,
    int m0, int n0, __half* smh, float acc[4][4][4])
{
    const int tid = threadIdx.x;
    const int wid = tid >> 5;
    const int lane = tid & 31;
    const int m_warp = (wid >> 2) * 64;
    const int n_warp = (wid & 3) * 32;

    const int g8 = lane >> 3;
    const int r8 = lane & 7;
    const int a_row_l = r8 + (g8 & 1) * 8;
    const int a_kb    = (g8 >> 1) * 16;
    const int b_row_l = r8 + (g8 >> 1) * 8;
    const int b_kb    = (g8 & 1) * 16;

    const uint32_t smb = smem_u32(smh);

#pragma unroll
    for (int i = 0; i < 4; i++)
#pragma unroll
        for (int j = 0; j < 4; j++)
#pragma unroll
            for (int k = 0; k < 4; k++) acc[i][j][k] = 0.f;

    auto load_stage = [&](int kc, int s) {
        const __half* gA = A + (size_t)m0 * Cc + kc * BKH;
        const __half* gB = B + (size_t)n0 * Cc + kc * BKH;
        uint32_t dA = smb + (uint32_t)(s * STAGEH) * 2;
        uint32_t dB = dA + (uint32_t)TILEH * 2;
#pragma unroll
        for (int i = 0; i < 4; i++) {
            int idx = tid + i * 256;
            int row = idx >> 3;
            int c8 = idx & 7;
            CP_ASYNC16(dA + (uint32_t)(row * ASTRH + c8 * 8) * 2, gA + (size_t)row * Cc + c8 * 8);
        }
#pragma unroll
        for (int i = 0; i < 4; i++) {
            int idx = tid + i * 256;
            int row = idx >> 3;
            int c8 = idx & 7;
            CP_ASYNC16(dB + (uint32_t)(row * ASTRH + c8 * 8) * 2, gB + (size_t)row * Cc + c8 * 8);
        }
        CP_COMMIT();
    };

    load_stage(0, 0);
    load_stage(1, 1);

    for (int kt = 0; kt < NKH; kt++) {
        if (kt < NKH - 1) CP_WAIT(1); else CP_WAIT(0);
        __syncthreads();
        if (kt + 2 < NKH) load_stage(kt + 2, (kt + 2) % 3);

        const int s = kt % 3;
        const uint32_t aB = smb + (uint32_t)(s * STAGEH) * 2
                          + (uint32_t)((m_warp + a_row_l) * ASTRH) * 2 + a_kb;
        const uint32_t bB = smb + (uint32_t)(s * STAGEH + TILEH) * 2
                          + (uint32_t)((n_warp + b_row_l) * ASTRH) * 2 + b_kb;

#pragma unroll
        for (int ks = 0; ks < 4; ks++) {
            uint32_t af[4][4];
#pragma unroll
            for (int mi = 0; mi < 4; mi++)
                ldsm_x4(af[mi], aB + (uint32_t)(mi * 16 * ASTRH) * 2 + ks * 32);
            uint32_t bf[2][4];
#pragma unroll
            for (int p = 0; p < 2; p++)
                ldsm_x4(bf[p], bB + (uint32_t)(p * 16 * ASTRH) * 2 + ks * 32);
#pragma unroll
            for (int mi = 0; mi < 4; mi++) {
#pragma unroll
                for (int p = 0; p < 2; p++) {
                    mma_f16(acc[mi][p * 2 + 0], af[mi], bf[p][0], bf[p][1]);
                    mma_f16(acc[mi][p * 2 + 1], af[mi], bf[p][2], bf[p][3]);
                }
            }
        }
    }
}

__device__ __forceinline__ void epilogue_h(
    float acc[4][4][4], const float* bias, __half* outp, int m0, int n0, int act)
{
    const int tid = threadIdx.x;
    const int wid = tid >> 5;
    const int lane = tid & 31;
    const int m_warp = (wid >> 2) * 64;
    const int n_warp = (wid & 3) * 32;
    const int r_lo = lane >> 2;
    const int c_off = (lane & 3) * 2;
#pragma unroll
    for (int mi = 0; mi < 4; mi++) {
#pragma unroll
        for (int nj = 0; nj < 4; nj++) {
            int col = n0 + n_warp + nj * 8 + c_off;
            float b0 = bias[col], b1 = bias[col + 1];
#pragma unroll
            for (int half_ = 0; half_ < 2; half_++) {
                int row = m0 + m_warp + mi * 16 + r_lo + half_ * 8;
                float v0 = acc[mi][nj][half_ * 2 + 0] + b0;
                float v1 = acc[mi][nj][half_ * 2 + 1] + b1;
                if (act) {
                    v0 = (v0 > 0.f) ? v0 + 1.f : expf(v0);
                    v1 = (v1 > 0.f) ? v1 + 1.f : expf(v1);
                }
                __half2 hv = __floats2half2_rn(v0, v1);
                *(__half2*)(outp + (size_t)row * Cc + col) = hv;
            }
        }
    }
}

// Fused QKV projection: grid (NN/BM, 12). Segment = by>>2: 0=Q,1=K,2=V.
__global__ __launch_bounds__(256, 2)
void gemm_qkv(const __half* __restrict__ X, const __half* __restrict__ W,
              const float* __restrict__ bq, const float* __restrict__ bk,
              const float* __restrict__ bv,
              __half* __restrict__ Q, __half* __restrict__ K, __half* __restrict__ V)
{
    extern __shared__ __half smh[];
    const int seg = blockIdx.y >> 2;
    const int n0 = (blockIdx.y & 3) * BN;
    const int m0 = blockIdx.x * BM;

    const __half* B = W + (size_t)seg * Cc * Cc;
    const float* bias = (seg == 0) ? bq : (seg == 1) ? bk : bv;
    __half* outp = (seg == 0) ? Q : (seg == 1) ? K : V;
    const int act = (seg < 2);

    float acc[4][4][4];
    gemm_core(X, B, m0, n0, smh, acc);
    epilogue_h(acc, bias, outp, m0, n0, act);
}

// Output projection: f32 store, no activation.
__global__ __launch_bounds__(256, 2)
void gemm_out(const __half* __restrict__ Y, const __half* __restrict__ W,
              const float* __restrict__ bias, float* __restrict__ outp)
{
    extern __shared__ __half smh[];
    const int m0 = blockIdx.x * BM;
    const int n0 = blockIdx.y * BN;

    float acc[4][4][4];
    gemm_core(Y, W, m0, n0, smh, acc);

    const int tid = threadIdx.x;
    const int wid = tid >> 5;
    const int lane = tid & 31;
    const int m_warp = (wid >> 2) * 64;
    const int n_warp = (wid & 3) * 32;
    const int r_lo = lane >> 2;
    const int c_off = (lane & 3) * 2;
#pragma unroll
    for (int mi = 0; mi < 4; mi++) {
#pragma unroll
        for (int nj = 0; nj < 4; nj++) {
            int col = n0 + n_warp + nj * 8 + c_off;
            float b0 = bias[col], b1 = bias[col + 1];
#pragma unroll
            for (int half_ = 0; half_ < 2; half_++) {
                int row = m0 + m_warp + mi * 16 + r_lo + half_ * 8;
                float v0 = acc[mi][nj][half_ * 2 + 0] + b0;
                float v1 = acc[mi][nj][half_ * 2 + 1] + b1;
                *(float2*)(outp + (size_t)row * Cc + col) = make_float2(v0, v1);
            }
        }
    }
}

// ---------------- fused f32 -> f16 conversion (x + all 4 W) ----------------
#define N8X (NN * Cc / 8)
#define W8  (Cc * Cc / 8)
__global__ __launch_bounds__(256) void cvt_all(
    const float4* __restrict__ x,
    const float4* __restrict__ w0, const float4* __restrict__ w1,
    const float4* __restrict__ w2, const float4* __restrict__ w3,
    uint4* __restrict__ dx, uint4* __restrict__ dw)
{
    int i = blockIdx.x * blockDim.x + threadIdx.x;
    const float4* src;
    uint4* dst;
    int j;
    if (i < N8X) {
        src = x; dst = dx; j = i;
    } else {
        int k = i - N8X;
        if (k >= 4 * W8) return;
        int seg = k / W8;
        j = k - seg * W8;
        src = (seg == 0) ? w0 : (seg == 1) ? w1 : (seg == 2) ? w2 : w3;
        dst = dw + (size_t)seg * W8;
    }
    float4 a = src[2 * j], b = src[2 * j + 1];
    __half2 h0 = __floats2half2_rn(a.x, a.y);
    __half2 h1 = __floats2half2_rn(a.z, a.w);
    __half2 h2 = __floats2half2_rn(b.x, b.y);
    __half2 h3 = __floats2half2_rn(b.z, b.w);
    uint4 o;
    o.x = *(uint32_t*)&h0; o.y = *(uint32_t*)&h1;
    o.z = *(uint32_t*)&h2; o.w = *(uint32_t*)&h3;
    dst[j] = o;
}

// ---------------- tensor-core KV accumulation (pipelined, 256 thr) ----------------
#define KSTR 72
#define KTILEH (64 * KSTR)
#define KSTAGEH (2 * KTILEH)
__global__ __launch_bounds__(256) void kv_mma()
{
    const int bh = blockIdx.x;
    const int b = bh >> 3, h = bh & 7;
    const int split = blockIdx.y;
    const int tid = threadIdx.x;
    const int wid = tid >> 5;
    const int lane = tid & 31;
    const size_t base = ((size_t)b * Tt + (size_t)split * KVROWS) * Cc + h * Dd;

    __shared__ __align__(16) __half sm[2 * KSTAGEH];
    __shared__ float sKs4[4][64];
    const uint32_t smb = smem_u32(sm);

    const int e_w = (wid & 3) * 16;
    const int d_w = (wid >> 2) * 32;

    const int g8 = lane >> 3;
    const int r8 = lane & 7;
    const uint32_t aOff = (uint32_t)(((g8 >> 1) * 8 + r8) * KSTR + e_w + (g8 & 1) * 8) * 2;
    const uint32_t bOff = (uint32_t)(((g8 & 1) * 8 + r8) * KSTR + d_w + (g8 >> 1) * 8) * 2;

    const int ks_d = tid & 63;
    const int ks_r0 = (tid >> 6) * 16;

    auto load_chunk = [&](int c0, int s) {
        uint32_t dK = smb + (uint32_t)(s * KSTAGEH) * 2;
        uint32_t dV = dK + (uint32_t)KTILEH * 2;
#pragma unroll
        for (int i = 0; i < 2; i++) {
            int idx = tid + i * 256;
            int row = idx >> 3;
            int c8 = idx & 7;
            CP_ASYNC16(dK + (uint32_t)(row * KSTR + c8 * 8) * 2,
                       g_Kh + base + (size_t)(c0 + row) * Cc + c8 * 8);
            CP_ASYNC16(dV + (uint32_t)(row * KSTR + c8 * 8) * 2,
                       g_Vh + base + (size_t)(c0 + row) * Cc + c8 * 8);
        }
        CP_COMMIT();
    };

    float acc[4][4];
#pragma unroll
    for (int j = 0; j < 4; j++)
#pragma unroll
        for (int k = 0; k < 4; k++) acc[j][k] = 0.f;
    float ks = 0.f;

    load_chunk(0, 0);

    const int NCH = KVROWS / 64;   // 16
    for (int c = 0; c < NCH; c++) {
        if (c + 1 < NCH) {
            load_chunk((c + 1) * 64, (c + 1) & 1);
            CP_WAIT(1);
        } else {
            CP_WAIT(0);
        }
        __syncthreads();

        const int s = c & 1;
        const uint32_t sKb = smb + (uint32_t)(s * KSTAGEH) * 2;
        const uint32_t sVb = sKb + (uint32_t)KTILEH * 2;
        const __half* sKh = sm + s * KSTAGEH;

#pragma unroll
        for (int r = 0; r < 16; r++)
            ks += __half2float(sKh[(ks_r0 + r) * KSTR + ks_d]);

#pragma unroll
        for (int kt = 0; kt < 4; kt++) {
            uint32_t af[4];
            ldsm_x4_t(af, sVb + aOff + (uint32_t)(kt * 16 * KSTR) * 2);
            uint32_t bf[2][4];
#pragma unroll
            for (int p = 0; p < 2; p++)
                ldsm_x4_t(bf[p], sKb + bOff + (uint32_t)(kt * 16 * KSTR) * 2 + p * 32);
#pragma unroll
            for (int p = 0; p < 2; p++) {
                mma_f16(acc[p * 2 + 0], af, bf[p][0], bf[p][1]);
                mma_f16(acc[p * 2 + 1], af, bf[p][2], bf[p][3]);
            }
        }
        __syncthreads();
    }

    float* kvp = g_KVp + ((size_t)split * BH + bh) * (Dd * Dd);
    const int r_lo = lane >> 2;
    const int c_off = (lane & 3) * 2;
#pragma unroll
    for (int nj = 0; nj < 4; nj++) {
        int d = d_w + nj * 8 + c_off;
#pragma unroll
        for (int half_ = 0; half_ < 2; half_++) {
            int e = e_w + r_lo + half_ * 8;
            *(float2*)(kvp + e * Dd + d) =
                make_float2(acc[nj][half_ * 2 + 0], acc[nj][half_ * 2 + 1]);
        }
    }
    sKs4[tid >> 6][ks_d] = ks;
    __syncthreads();
    if (tid < 64)
        g_Ksp[((size_t)split * BH + bh) * Dd + tid] =
            sKs4[0][tid] + sKs4[1][tid] + sKs4[2][tid] + sKs4[3][tid];
}

// Reduce partials -> Ksum (fp32) and KVt (fp16, already [e][d]). grid = BH.
__global__ __launch_bounds__(256) void kv_reduce()
{
    const int bh = blockIdx.x;
    const int tid = threadIdx.x;

#pragma unroll
    for (int j = 0; j < 16; j++) {
        int idx = j * 256 + tid;
        float s = 0.f;
#pragma unroll
        for (int p = 0; p < KV_SPLIT; p++)
            s += g_KVp[((size_t)p * BH + bh) * (Dd * Dd) + idx];
        g_KVt[(size_t)bh * (Dd * Dd) + idx] = __float2half(s);
    }
    if (tid < 64) {
        float s = 0.f;
#pragma unroll
        for (int p = 0; p < KV_SPLIT; p++)
            s += g_Ksp[((size_t)p * BH + bh) * Dd + tid];
        g_Ksum[bh * Dd + tid] = s;
    }
}

// ---------------- tensor-core Y kernel (pipelined over 4 Q sub-tiles) ----------------
// grid (Tt/256, BH), 128 threads. KVt/Ksum loaded once per CTA.
#define YSTR 72
__global__ __launch_bounds__(128) void y_mma()
{
    const int bh = blockIdx.y;
    const int b = bh >> 3, h = bh & 7;
    const int t0 = blockIdx.x * 256;
    const int tid = threadIdx.x;
    const int wid = tid >> 5;
    const int lane = tid & 31;

    __shared__ __align__(16) __half sB[64 * YSTR];
    __shared__ __align__(16) __half sQ[2][64 * YSTR];
    __shared__ float sKs[64];
    __shared__ float sInv[64];

    // KVt + Ksum once
#pragma unroll
    for (int i = 0; i < 4; i++) {
        int idx = tid + i * 128;
        int row = idx >> 3;
        int c8 = idx & 7;
        *(uint4*)(sB + row * YSTR + c8 * 8) =
            *(const uint4*)(g_KVt + (size_t)bh * (Dd * Dd) + (size_t)row * Dd + c8 * 8);
    }
    if (tid < 64) sKs[tid] = g_Ksum[bh * Dd + tid];

    auto load_q = [&](int t) {
        uint32_t dst = smem_u32(sQ[t & 1]);
        const __half* src = g_Qh + ((size_t)b * Tt + t0 + t * 64) * Cc + h * Dd;
#pragma unroll
        for (int i = 0; i < 4; i++) {
            int idx = tid + i * 128;
            int row = idx >> 3;
            int c8 = idx & 7;
            CP_ASYNC16(dst + (uint32_t)(row * YSTR + c8 * 8) * 2,
                       src + (size_t)row * Cc + c8 * 8);
        }
        CP_COMMIT();
    };

    load_q(0);

    const int g8 = lane >> 3;
    const int r8 = lane & 7;
    const int a_row_l = r8 + (g8 & 1) * 8;
    const int a_kb    = (g8 >> 1) * 16;
    const int b_row_l = r8 + (g8 >> 1) * 8;
    const int b_kb    = (g8 & 1) * 16;
    const uint32_t bB = smem_u32(sB) + (uint32_t)(b_row_l * YSTR) * 2 + b_kb;

    const int r_lo = lane >> 2;
    const int c_off = (lane & 3) * 2;

    for (int t = 0; t < 4; t++) {
        // all warps finished tile t-1's reads of buffer (t+1)&1; sB/sKs visible after 1st pass
        __syncthreads();
        if (t + 1 < 4) {
            load_q(t + 1);
            CP_WAIT(1);
        } else {
            CP_WAIT(0);
        }
        __syncthreads();                    // tile t visible to all threads

        const __half* sQt = sQ[t & 1];
        if (tid < 64) {
            float s = 0.f;
#pragma unroll
            for (int d = 0; d < 64; d++)
                s = fmaf(__half2float(sQt[tid * YSTR + d]), sKs[d], s);
            sInv[tid] = 1.f / (s + 1e-6f);
        }
        __syncthreads();                    // sInv ready

        const uint32_t qB = smem_u32(sQt)
                          + (uint32_t)((wid * 16 + a_row_l) * YSTR) * 2 + a_kb;

        float acc[8][4];
#pragma unroll
        for (int j = 0; j < 8; j++)
#pragma unroll
            for (int k = 0; k < 4; k++) acc[j][k] = 0.f;

#pragma unroll
        for (int ks = 0; ks < 4; ks++) {
            uint32_t af[4];
            ldsm_x4(af, qB + ks * 32);
            uint32_t bf[4][4];
#pragma unroll
            for (int p = 0; p < 4; p++)
                ldsm_x4(bf[p], bB + (uint32_t)(p * 16 * YSTR) * 2 + ks * 32);
#pragma unroll
            for (int p = 0; p < 4; p++) {
                mma_f16(acc[p * 2 + 0], af, bf[p][0], bf[p][1]);
                mma_f16(acc[p * 2 + 1], af, bf[p][2], bf[p][3]);
            }
        }

#pragma unroll
        for (int nj = 0; nj < 8; nj++) {
            int col = nj * 8 + c_off;
#pragma unroll
            for (int half_ = 0; half_ < 2; half_++) {
                int tok = wid * 16 + r_lo + half_ * 8;
                float inv = sInv[tok];
                __half2 hv = __floats2half2_rn(acc[nj][half_ * 2 + 0] * inv,
                                               acc[nj][half_ * 2 + 1] * inv);
                *(__half2*)(g_Yh + ((size_t)b * Tt + t0 + t * 64 + tok) * Cc + h * Dd + col) = hv;
            }
        }
    }
}

// ---------------- launch ----------------
extern "C" void kernel_launch(void* const* d_in, const int* in_sizes, int n_in,
                              void* d_out, int out_size)
{
    const float* x  = (const float*)d_in[0];
    const float* Wq = (const float*)d_in[1];
    const float* bq = (const float*)d_in[2];
    const float* Wk = (const float*)d_in[3];
    const float* bk = (const float*)d_in[4];
    const float* Wv = (const float*)d_in[5];
    const float* bv = (const float*)d_in[6];
    const float* Wo = (const float*)d_in[7];
    const float* bo = (const float*)d_in[8];
    float* out = (float*)d_out;

    static __half *pXh = nullptr, *pWh, *pQh, *pKh, *pVh, *pYh;
    static bool inited = false;
    if (!inited) {
        cudaGetSymbolAddress((void**)&pXh, g_Xh);
        cudaGetSymbolAddress((void**)&pWh, g_Wh);
        cudaGetSymbolAddress((void**)&pQh, g_Qh);
        cudaGetSymbolAddress((void**)&pKh, g_Kh);
        cudaGetSymbolAddress((void**)&pVh, g_Vh);
        cudaGetSymbolAddress((void**)&pYh, g_Yh);
        cudaFuncSetAttribute(gemm_qkv, cudaFuncAttributeMaxDynamicSharedMemorySize, GEMM_SMEM);
        cudaFuncSetAttribute(gemm_out, cudaFuncAttributeMaxDynamicSharedMemorySize, GEMM_SMEM);
        inited = true;
    }

    // fused f32 -> f16 conversion (x + 4 weight matrices)
    {
        int tot = N8X + 4 * W8;
        cvt_all<<<(tot + 255) / 256, 256>>>((const float4*)x,
                                            (const float4*)Wq, (const float4*)Wk,
                                            (const float4*)Wv, (const float4*)Wo,
                                            (uint4*)pXh, (uint4*)pWh);
    }

    // Fused Q/K/V projections
    gemm_qkv<<<dim3(NN / BM, 12), 256, GEMM_SMEM>>>(pXh, pWh, bq, bk, bv, pQh, pKh, pVh);

    // Tensor-core KV accumulation (pipelined) -> reduce -> tensor-core Y (pipelined)
    kv_mma<<<dim3(BH, KV_SPLIT), 256>>>();
    kv_reduce<<<BH, 256>>>();
    y_mma<<<dim3(Tt / 256, BH), 128>>>();

    // Output projection
    gemm_out<<<dim3(NN / BM, Cc / BN), 256, GEMM_SMEM>>>(pYh, pWh + 3 * (size_t)Cc * Cc, bo, out);
}

// round 15
// speedup vs baseline: 2.0585x; 1.0089x over previous
#include <cuda_runtime.h>
#include <cuda_fp16.h>
#include <math.h>
#include <stdint.h>

// ---------------- Problem constants ----------------
#define Bb 8
#define Tt 8192
#define Cc 512
#define Hh 8
#define Dd 64
#define NN (Bb*Tt)         // 65536 tokens
#define BH (Bb*Hh)         // 64
#define KV_SPLIT 8
#define KVROWS (Tt / KV_SPLIT)   // 1024

// ---------------- Scratch (device globals) ----------------
__device__ __half g_Xh[(size_t)NN*Cc];
__device__ __half g_Wh[(size_t)4*Cc*Cc];
__device__ __half g_Qh[(size_t)NN*Cc];
__device__ __half g_Kh[(size_t)NN*Cc];
__device__ __half g_Vh[(size_t)NN*Cc];
__device__ __half g_Yh[(size_t)NN*Cc];
__device__ float  g_KVp[(size_t)KV_SPLIT*BH*Dd*Dd];   // partial KVt sums ([e][d] order)
__device__ float  g_Ksp[(size_t)KV_SPLIT*BH*Dd];      // partial Ksum
__device__ __half g_KVt[(size_t)BH*Dd*Dd];            // KV^T (e-major) fp16
__device__ float  g_Ksum[(size_t)BH*Dd];

// ---------------- helpers ----------------
__device__ __forceinline__ uint32_t smem_u32(const void* p) {
    uint32_t a;
    asm("{ .reg .u64 t; cvta.to.shared.u64 t, %1; cvt.u32.u64 %0, t; }" : "=r"(a) : "l"(p));
    return a;
}
#define CP_ASYNC16(dst, src) \
    asm volatile("cp.async.cg.shared.global [%0], [%1], 16;" :: "r"(dst), "l"(src) : "memory")
#define CP_COMMIT() asm volatile("cp.async.commit_group;" ::: "memory")
#define CP_WAIT(n)  asm volatile("cp.async.wait_group %0;" :: "n"(n) : "memory")

__device__ __forceinline__ void ldsm_x4(uint32_t* r, uint32_t addr) {
    asm volatile("ldmatrix.sync.aligned.m8n8.x4.shared.b16 {%0,%1,%2,%3}, [%4];"
                 : "=r"(r[0]), "=r"(r[1]), "=r"(r[2]), "=r"(r[3]) : "r"(addr));
}
__device__ __forceinline__ void ldsm_x4_t(uint32_t* r, uint32_t addr) {
    asm volatile("ldmatrix.sync.aligned.m8n8.x4.trans.shared.b16 {%0,%1,%2,%3}, [%4];"
                 : "=r"(r[0]), "=r"(r[1]), "=r"(r[2]), "=r"(r[3]) : "r"(addr));
}
__device__ __forceinline__ void mma_f16(float* c, const uint32_t* a, uint32_t b0, uint32_t b1) {
    asm volatile("mma.sync.aligned.m16n8k16.row.col.f32.f16.f16.f32 "
                 "{%0,%1,%2,%3},{%4,%5,%6,%7},{%8,%9},{%0,%1,%2,%3};"
                 : "+f"(c[0]), "+f"(c[1]), "+f"(c[2]), "+f"(c[3])
                 : "r"(a[0]), "r"(a[1]), "r"(a[2]), "r"(a[3]), "r"(b0), "r"(b1));
}

// ---------------- GEMM config (fp16, 128x128 CTA, 8 warps of 64x32) ----------------
#define BM 128
#define BN 128
#define BKH 64
#define NKH (Cc / BKH)
#define ASTRH 72
#define TILEH (BM * ASTRH)
#define STAGEH (2 * TILEH)
#define NSTG 3
#define GEMM_SMEM (NSTG * STAGEH * 2)   // 110592 bytes

__device__ __forceinline__ void gemm_core(
    const __half* __restrict__ A, const __half* __restrict__ B,
    int m0, int n0, __half* smh, float acc[4][4][4])
{
    const int tid = threadIdx.x;
    const int wid = tid >> 5;
    const int lane = tid & 31;
    const int m_warp = (wid >> 2) * 64;
    const int n_warp = (wid & 3) * 32;

    const int g8 = lane >> 3;
    const int r8 = lane & 7;
    const int a_row_l = r8 + (g8 & 1) * 8;
    const int a_kb    = (g8 >> 1) * 16;
    const int b_row_l = r8 + (g8 >> 1) * 8;
    const int b_kb    = (g8 & 1) * 16;

    const uint32_t smb = smem_u32(smh);

#pragma unroll
    for (int i = 0; i < 4; i++)
#pragma unroll
        for (int j = 0; j < 4; j++)
#pragma unroll
            for (int k = 0; k < 4; k++) acc[i][j][k] = 0.f;

    auto load_stage = [&](int kc, int s) {
        const __half* gA = A + (size_t)m0 * Cc + kc * BKH;
        const __half* gB = B + (size_t)n0 * Cc + kc * BKH;
        uint32_t dA = smb + (uint32_t)(s * STAGEH) * 2;
        uint32_t dB = dA + (uint32_t)TILEH * 2;
#pragma unroll
        for (int i = 0; i < 4; i++) {
            int idx = tid + i * 256;
            int row = idx >> 3;
            int c8 = idx & 7;
            CP_ASYNC16(dA + (uint32_t)(row * ASTRH + c8 * 8) * 2, gA + (size_t)row * Cc + c8 * 8);
        }
#pragma unroll
        for (int i = 0; i < 4; i++) {
            int idx = tid + i * 256;
            int row = idx >> 3;
            int c8 = idx & 7;
            CP_ASYNC16(dB + (uint32_t)(row * ASTRH + c8 * 8) * 2, gB + (size_t)row * Cc + c8 * 8);
        }
        CP_COMMIT();
    };

    load_stage(0, 0);
    load_stage(1, 1);

    for (int kt = 0; kt < NKH; kt++) {
        if (kt < NKH - 1) CP_WAIT(1); else CP_WAIT(0);
        __syncthreads();
        if (kt + 2 < NKH) load_stage(kt + 2, (kt + 2) % 3);

        const int s = kt % 3;
        const uint32_t aB = smb + (uint32_t)(s * STAGEH) * 2
                          + (uint32_t)((m_warp + a_row_l) * ASTRH) * 2 + a_kb;
        const uint32_t bB = smb + (uint32_t)(s * STAGEH + TILEH) * 2
                          + (uint32_t)((n_warp + b_row_l) * ASTRH) * 2 + b_kb;

#pragma unroll
        for (int ks = 0; ks < 4; ks++) {
            uint32_t af[4][4];
#pragma unroll
            for (int mi = 0; mi < 4; mi++)
                ldsm_x4(af[mi], aB + (uint32_t)(mi * 16 * ASTRH) * 2 + ks * 32);
            uint32_t bf[2][4];
#pragma unroll
            for (int p = 0; p < 2; p++)
                ldsm_x4(bf[p], bB + (uint32_t)(p * 16 * ASTRH) * 2 + ks * 32);
#pragma unroll
            for (int mi = 0; mi < 4; mi++) {
#pragma unroll
                for (int p = 0; p < 2; p++) {
                    mma_f16(acc[mi][p * 2 + 0], af[mi], bf[p][0], bf[p][1]);
                    mma_f16(acc[mi][p * 2 + 1], af[mi], bf[p][2], bf[p][3]);
                }
            }
        }
    }
}

__device__ __forceinline__ void epilogue_h(
    float acc[4][4][4], const float* bias, __half* outp, int m0, int n0, int act)
{
    const int tid = threadIdx.x;
    const int wid = tid >> 5;
    const int lane = tid & 31;
    const int m_warp = (wid >> 2) * 64;
    const int n_warp = (wid & 3) * 32;
    const int r_lo = lane >> 2;
    const int c_off = (lane & 3) * 2;
#pragma unroll
    for (int mi = 0; mi < 4; mi++) {
#pragma unroll
        for (int nj = 0; nj < 4; nj++) {
            int col = n0 + n_warp + nj * 8 + c_off;
            float b0 = bias[col], b1 = bias[col + 1];
#pragma unroll
            for (int half_ = 0; half_ < 2; half_++) {
                int row = m0 + m_warp + mi * 16 + r_lo + half_ * 8;
                float v0 = acc[mi][nj][half_ * 2 + 0] + b0;
                float v1 = acc[mi][nj][half_ * 2 + 1] + b1;
                if (act) {
                    v0 = (v0 > 0.f) ? v0 + 1.f : expf(v0);
                    v1 = (v1 > 0.f) ? v1 + 1.f : expf(v1);
                }
                __half2 hv = __floats2half2_rn(v0, v1);
                *(__half2*)(outp + (size_t)row * Cc + col) = hv;
            }
        }
    }
}

// Fused QKV projection: grid (NN/BM, 12). Segment = by>>2: 0=Q,1=K,2=V.
__global__ __launch_bounds__(256, 2)
void gemm_qkv(const __half* __restrict__ X, const __half* __restrict__ W,
              const float* __restrict__ bq, const float* __restrict__ bk,
              const float* __restrict__ bv,
              __half* __restrict__ Q, __half* __restrict__ K, __half* __restrict__ V)
{
    extern __shared__ __half smh[];
    const int seg = blockIdx.y >> 2;
    const int n0 = (blockIdx.y & 3) * BN;
    const int m0 = blockIdx.x * BM;

    const __half* B = W + (size_t)seg * Cc * Cc;
    const float* bias = (seg == 0) ? bq : (seg == 1) ? bk : bv;
    __half* outp = (seg == 0) ? Q : (seg == 1) ? K : V;
    const int act = (seg < 2);

    float acc[4][4][4];
    gemm_core(X, B, m0, n0, smh, acc);
    epilogue_h(acc, bias, outp, m0, n0, act);
}

// Output projection: f32 store, no activation.
__global__ __launch_bounds__(256, 2)
void gemm_out(const __half* __restrict__ Y, const __half* __restrict__ W,
              const float* __restrict__ bias, float* __restrict__ outp)
{
    extern __shared__ __half smh[];
    const int m0 = blockIdx.x * BM;
    const int n0 = blockIdx.y * BN;

    float acc[4][4][4];
    gemm_core(Y, W, m0, n0, smh, acc);

    const int tid = threadIdx.x;
    const int wid = tid >> 5;
    const int lane = tid & 31;
    const int m_warp = (wid >> 2) * 64;
    const int n_warp = (wid & 3) * 32;
    const int r_lo = lane >> 2;
    const int c_off = (lane & 3) * 2;
#pragma unroll
    for (int mi = 0; mi < 4; mi++) {
#pragma unroll
        for (int nj = 0; nj < 4; nj++) {
            int col = n0 + n_warp + nj * 8 + c_off;
            float b0 = bias[col], b1 = bias[col + 1];
#pragma unroll
            for (int half_ = 0; half_ < 2; half_++) {
                int row = m0 + m_warp + mi * 16 + r_lo + half_ * 8;
                float v0 = acc[mi][nj][half_ * 2 + 0] + b0;
                float v1 = acc[mi][nj][half_ * 2 + 1] + b1;
                *(float2*)(outp + (size_t)row * Cc + col) = make_float2(v0, v1);
            }
        }
    }
}

// ---------------- fused f32 -> f16 conversion (x + all 4 W) ----------------
#define N8X (NN * Cc / 8)
#define W8  (Cc * Cc / 8)
__global__ __launch_bounds__(256) void cvt_all(
    const float4* __restrict__ x,
    const float4* __restrict__ w0, const float4* __restrict__ w1,
    const float4* __restrict__ w2, const float4* __restrict__ w3,
    uint4* __restrict__ dx, uint4* __restrict__ dw)
{
    int i = blockIdx.x * blockDim.x + threadIdx.x;
    const float4* src;
    uint4* dst;
    int j;
    if (i < N8X) {
        src = x; dst = dx; j = i;
    } else {
        int k = i - N8X;
        if (k >= 4 * W8) return;
        int seg = k / W8;
        j = k - seg * W8;
        src = (seg == 0) ? w0 : (seg == 1) ? w1 : (seg == 2) ? w2 : w3;
        dst = dw + (size_t)seg * W8;
    }
    float4 a = src[2 * j], b = src[2 * j + 1];
    __half2 h0 = __floats2half2_rn(a.x, a.y);
    __half2 h1 = __floats2half2_rn(a.z, a.w);
    __half2 h2 = __floats2half2_rn(b.x, b.y);
    __half2 h3 = __floats2half2_rn(b.z, b.w);
    uint4 o;
    o.x = *(uint32_t*)&h0; o.y = *(uint32_t*)&h1;
    o.z = *(uint32_t*)&h2; o.w = *(uint32_t*)&h3;
    dst[j] = o;
}

// ---------------- tensor-core KV accumulation (pipelined, 256 thr) ----------------
#define KSTR 72
#define KTILEH (64 * KSTR)
#define KSTAGEH (2 * KTILEH)
__global__ __launch_bounds__(256) void kv_mma()
{
    const int bh = blockIdx.x;
    const int b = bh >> 3, h = bh & 7;
    const int split = blockIdx.y;
    const int tid = threadIdx.x;
    const int wid = tid >> 5;
    const int lane = tid & 31;
    const size_t base = ((size_t)b * Tt + (size_t)split * KVROWS) * Cc + h * Dd;

    __shared__ __align__(16) __half sm[2 * KSTAGEH];
    __shared__ float sKs4[4][64];
    const uint32_t smb = smem_u32(sm);

    const int e_w = (wid & 3) * 16;
    const int d_w = (wid >> 2) * 32;

    const int g8 = lane >> 3;
    const int r8 = lane & 7;
    const uint32_t aOff = (uint32_t)(((g8 >> 1) * 8 + r8) * KSTR + e_w + (g8 & 1) * 8) * 2;
    const uint32_t bOff = (uint32_t)(((g8 & 1) * 8 + r8) * KSTR + d_w + (g8 >> 1) * 8) * 2;

    const int ks_d = tid & 63;
    const int ks_r0 = (tid >> 6) * 16;

    auto load_chunk = [&](int c0, int s) {
        uint32_t dK = smb + (uint32_t)(s * KSTAGEH) * 2;
        uint32_t dV = dK + (uint32_t)KTILEH * 2;
#pragma unroll
        for (int i = 0; i < 2; i++) {
            int idx = tid + i * 256;
            int row = idx >> 3;
            int c8 = idx & 7;
            CP_ASYNC16(dK + (uint32_t)(row * KSTR + c8 * 8) * 2,
                       g_Kh + base + (size_t)(c0 + row) * Cc + c8 * 8);
            CP_ASYNC16(dV + (uint32_t)(row * KSTR + c8 * 8) * 2,
                       g_Vh + base + (size_t)(c0 + row) * Cc + c8 * 8);
        }
        CP_COMMIT();
    };

    float acc[4][4];
#pragma unroll
    for (int j = 0; j < 4; j++)
#pragma unroll
        for (int k = 0; k < 4; k++) acc[j][k] = 0.f;
    float ks = 0.f;

    load_chunk(0, 0);

    const int NCH = KVROWS / 64;   // 16
    for (int c = 0; c < NCH; c++) {
        if (c + 1 < NCH) {
            load_chunk((c + 1) * 64, (c + 1) & 1);
            CP_WAIT(1);
        } else {
            CP_WAIT(0);
        }
        __syncthreads();

        const int s = c & 1;
        const uint32_t sKb = smb + (uint32_t)(s * KSTAGEH) * 2;
        const uint32_t sVb = sKb + (uint32_t)KTILEH * 2;
        const __half* sKh = sm + s * KSTAGEH;

#pragma unroll
        for (int r = 0; r < 16; r++)
            ks += __half2float(sKh[(ks_r0 + r) * KSTR + ks_d]);

#pragma unroll
        for (int kt = 0; kt < 4; kt++) {
            uint32_t af[4];
            ldsm_x4_t(af, sVb + aOff + (uint32_t)(kt * 16 * KSTR) * 2);
            uint32_t bf[2][4];
#pragma unroll
            for (int p = 0; p < 2; p++)
                ldsm_x4_t(bf[p], sKb + bOff + (uint32_t)(kt * 16 * KSTR) * 2 + p * 32);
#pragma unroll
            for (int p = 0; p < 2; p++) {
                mma_f16(acc[p * 2 + 0], af, bf[p][0], bf[p][1]);
                mma_f16(acc[p * 2 + 1], af, bf[p][2], bf[p][3]);
            }
        }
        __syncthreads();
    }

    float* kvp = g_KVp + ((size_t)split * BH + bh) * (Dd * Dd);
    const int r_lo = lane >> 2;
    const int c_off = (lane & 3) * 2;
#pragma unroll
    for (int nj = 0; nj < 4; nj++) {
        int d = d_w + nj * 8 + c_off;
#pragma unroll
        for (int half_ = 0; half_ < 2; half_++) {
            int e = e_w + r_lo + half_ * 8;
            *(float2*)(kvp + e * Dd + d) =
                make_float2(acc[nj][half_ * 2 + 0], acc[nj][half_ * 2 + 1]);
        }
    }
    sKs4[tid >> 6][ks_d] = ks;
    __syncthreads();
    if (tid < 64)
        g_Ksp[((size_t)split * BH + bh) * Dd + tid] =
            sKs4[0][tid] + sKs4[1][tid] + sKs4[2][tid] + sKs4[3][tid];
}

// Reduce partials -> Ksum (fp32) and KVt (fp16, [e][d]).
// grid (BH, 4): each CTA reduces a 1024-element slice; Ksum on slice 0.
__global__ __launch_bounds__(256) void kv_reduce()
{
    const int bh = blockIdx.x;
    const int tid = threadIdx.x;
    const int base = blockIdx.y * 1024;

#pragma unroll
    for (int j = 0; j < 4; j++) {
        int idx = base + j * 256 + tid;
        float s = 0.f;
#pragma unroll
        for (int p = 0; p < KV_SPLIT; p++)
            s += g_KVp[((size_t)p * BH + bh) * (Dd * Dd) + idx];
        g_KVt[(size_t)bh * (Dd * Dd) + idx] = __float2half(s);
    }
    if (blockIdx.y == 0 && tid < 64) {
        float s = 0.f;
#pragma unroll
        for (int p = 0; p < KV_SPLIT; p++)
            s += g_Ksp[((size_t)p * BH + bh) * Dd + tid];
        g_Ksum[bh * Dd + tid] = s;
    }
}

// ---------------- tensor-core Y kernel (pipelined over 4 Q sub-tiles) ----------------
#define YSTR 72
__global__ __launch_bounds__(128) void y_mma()
{
    const int bh = blockIdx.y;
    const int b = bh >> 3, h = bh & 7;
    const int t0 = blockIdx.x * 256;
    const int tid = threadIdx.x;
    const int wid = tid >> 5;
    const int lane = tid & 31;

    __shared__ __align__(16) __half sB[64 * YSTR];
    __shared__ __align__(16) __half sQ[2][64 * YSTR];
    __shared__ float sKs[64];
    __shared__ float sInv[64];

#pragma unroll
    for (int i = 0; i < 4; i++) {
        int idx = tid + i * 128;
        int row = idx >> 3;
        int c8 = idx & 7;
        *(uint4*)(sB + row * YSTR + c8 * 8) =
            *(const uint4*)(g_KVt + (size_t)bh * (Dd * Dd) + (size_t)row * Dd + c8 * 8);
    }
    if (tid < 64) sKs[tid] = g_Ksum[bh * Dd + tid];

    auto load_q = [&](int t) {
        uint32_t dst = smem_u32(sQ[t & 1]);
        const __half* src = g_Qh + ((size_t)b * Tt + t0 + t * 64) * Cc + h * Dd;
#pragma unroll
        for (int i = 0; i < 4; i++) {
            int idx = tid + i * 128;
            int row = idx >> 3;
            int c8 = idx & 7;
            CP_ASYNC16(dst + (uint32_t)(row * YSTR + c8 * 8) * 2,
                       src + (size_t)row * Cc + c8 * 8);
        }
        CP_COMMIT();
    };

    load_q(0);

    const int g8 = lane >> 3;
    const int r8 = lane & 7;
    const int a_row_l = r8 + (g8 & 1) * 8;
    const int a_kb    = (g8 >> 1) * 16;
    const int b_row_l = r8 + (g8 >> 1) * 8;
    const int b_kb    = (g8 & 1) * 16;
    const uint32_t bB = smem_u32(sB) + (uint32_t)(b_row_l * YSTR) * 2 + b_kb;

    const int r_lo = lane >> 2;
    const int c_off = (lane & 3) * 2;

    for (int t = 0; t < 4; t++) {
        __syncthreads();
        if (t + 1 < 4) {
            load_q(t + 1);
            CP_WAIT(1);
        } else {
            CP_WAIT(0);
        }
        __syncthreads();

        const __half* sQt = sQ[t & 1];
        if (tid < 64) {
            float s = 0.f;
#pragma unroll
            for (int d = 0; d < 64; d++)
                s = fmaf(__half2float(sQt[tid * YSTR + d]), sKs[d], s);
            sInv[tid] = 1.f / (s + 1e-6f);
        }
        __syncthreads();

        const uint32_t qB = smem_u32(sQt)
                          + (uint32_t)((wid * 16 + a_row_l) * YSTR) * 2 + a_kb;

        float acc[8][4];
#pragma unroll
        for (int j = 0; j < 8; j++)
#pragma unroll
            for (int k = 0; k < 4; k++) acc[j][k] = 0.f;

#pragma unroll
        for (int ks = 0; ks < 4; ks++) {
            uint32_t af[4];
            ldsm_x4(af, qB + ks * 32);
            uint32_t bf[4][4];
#pragma unroll
            for (int p = 0; p < 4; p++)
                ldsm_x4(bf[p], bB + (uint32_t)(p * 16 * YSTR) * 2 + ks * 32);
#pragma unroll
            for (int p = 0; p < 4; p++) {
                mma_f16(acc[p * 2 + 0], af, bf[p][0], bf[p][1]);
                mma_f16(acc[p * 2 + 1], af, bf[p][2], bf[p][3]);
            }
        }

#pragma unroll
        for (int nj = 0; nj < 8; nj++) {
            int col = nj * 8 + c_off;
#pragma unroll
            for (int half_ = 0; half_ < 2; half_++) {
                int tok = wid * 16 + r_lo + half_ * 8;
                float inv = sInv[tok];
                __half2 hv = __floats2half2_rn(acc[nj][half_ * 2 + 0] * inv,
                                               acc[nj][half_ * 2 + 1] * inv);
                *(__half2*)(g_Yh + ((size_t)b * Tt + t0 + t * 64 + tok) * Cc + h * Dd + col) = hv;
            }
        }
    }
}

// ---------------- launch ----------------
extern "C" void kernel_launch(void* const* d_in, const int* in_sizes, int n_in,
                              void* d_out, int out_size)
{
    const float* x  = (const float*)d_in[0];
    const float* Wq = (const float*)d_in[1];
    const float* bq = (const float*)d_in[2];
    const float* Wk = (const float*)d_in[3];
    const float* bk = (const float*)d_in[4];
    const float* Wv = (const float*)d_in[5];
    const float* bv = (const float*)d_in[6];
    const float* Wo = (const float*)d_in[7];
    const float* bo = (const float*)d_in[8];
    float* out = (float*)d_out;

    static __half *pXh = nullptr, *pWh, *pQh, *pKh, *pVh, *pYh;
    static bool inited = false;
    if (!inited) {
        cudaGetSymbolAddress((void**)&pXh, g_Xh);
        cudaGetSymbolAddress((void**)&pWh, g_Wh);
        cudaGetSymbolAddress((void**)&pQh, g_Qh);
        cudaGetSymbolAddress((void**)&pKh, g_Kh);
        cudaGetSymbolAddress((void**)&pVh, g_Vh);
        cudaGetSymbolAddress((void**)&pYh, g_Yh);
        cudaFuncSetAttribute(gemm_qkv, cudaFuncAttributeMaxDynamicSharedMemorySize, GEMM_SMEM);
        cudaFuncSetAttribute(gemm_out, cudaFuncAttributeMaxDynamicSharedMemorySize, GEMM_SMEM);
        inited = true;
    }

    // fused f32 -> f16 conversion (x + 4 weight matrices)
    {
        int tot = N8X + 4 * W8;
        cvt_all<<<(tot + 255) / 256, 256>>>((const float4*)x,
                                            (const float4*)Wq, (const float4*)Wk,
                                            (const float4*)Wv, (const float4*)Wo,
                                            (uint4*)pXh, (uint4*)pWh);
    }

    // Fused Q/K/V projections
    gemm_qkv<<<dim3(NN / BM, 12), 256, GEMM_SMEM>>>(pXh, pWh, bq, bk, bv, pQh, pKh, pVh);

    // Tensor-core KV accumulation (pipelined) -> wide reduce -> tensor-core Y (pipelined)
    kv_mma<<<dim3(BH, KV_SPLIT), 256>>>();
    kv_reduce<<<dim3(BH, 4), 256>>>();
    y_mma<<<dim3(Tt / 256, BH), 128>>>();

    // Output projection
    gemm_out<<<dim3(NN / BM, Cc / BN), 256, GEMM_SMEM>>>(pYh, pWh + 3 * (size_t)Cc * Cc, bo, out);
}